// round 11
// baseline (speedup 1.0000x reference)
#include <cuda_runtime.h>
#include <cuda_bf16.h>
#include <cuda_fp16.h>
#include <cstdint>
#include <math.h>

#define N_NODES   50000
#define NROWS     50048
#define N_EDGES   800000
#define NUM_GRAPHS 256
#define C         129
#define ZDIM      259
#define NLAYERS   5
#define XS        160
#define PLN       132
#define NCOL      264
#define NPG       288
#define P2S       320

// GEMM smem offsets
#define GSA    0
#define GSAL   43008
#define GSB    86016
#define GSSP   23040
#define GSBUF  46080
#define GSBI   178176
#define GSMEM  179328

__device__ __align__(16) __nv_bfloat16 d_wbN[NLAYERS*2*2*5*NPG*32];
__device__ float d_bph[NLAYERS*2*NPG];
__device__ float d_w3[NLAYERS*NCOL];
__device__ __align__(16) float d_xa[NROWS*XS];
__device__ __align__(16) float d_xb[NROWS*XS];
__device__ __align__(16) float  d_P1[(size_t)NROWS*NCOL];
__device__ __align__(16) __half d_P2h[(size_t)NROWS*P2S];
__device__ int   d_cnt[N_NODES];
__device__ int   d_rowptr[N_NODES + 1];
__device__ int   d_pos[N_NODES];
__device__ __align__(8) int2 d_edges[N_EDGES];
__device__ int   d_dh[256];
__device__ int   d_dpos[256];
__device__ int   d_order[N_NODES];
__device__ float d_gsum[NUM_GRAPHS*PLN];
__device__ float d_gcnt[NUM_GRAPHS];

__device__ __host__ __forceinline__ void colmap(int n, int& pl, int& j){
    pl = (n >> 1) & 1;
    j  = 2*(n >> 2) + (n & 1);
}

__device__ __forceinline__ uint32_t smem_u32(const void* p){
    uint32_t a;
    asm("{ .reg .u64 t; cvta.to.shared.u64 t, %1; cvt.u32.u64 %0, t; }" : "=r"(a) : "l"(p));
    return a;
}
__device__ __forceinline__ void mma16816(float* d, uint32_t a0, uint32_t a1,
                                         uint32_t a2, uint32_t a3,
                                         uint32_t b0, uint32_t b1){
    asm volatile(
        "mma.sync.aligned.m16n8k16.row.col.f32.bf16.bf16.f32 "
        "{%0,%1,%2,%3}, {%4,%5,%6,%7}, {%8,%9}, {%0,%1,%2,%3};"
        : "+f"(d[0]), "+f"(d[1]), "+f"(d[2]), "+f"(d[3])
        : "r"(a0), "r"(a1), "r"(a2), "r"(a3), "r"(b0), "r"(b1));
}
__device__ __forceinline__ void cpasync16(uint32_t s, const void* g){
    asm volatile("cp.async.cg.shared.global [%0], [%1], 16;" :: "r"(s), "l"(g));
}
__device__ __forceinline__ void red4(float* p, float4 v){
    asm volatile("red.global.add.v4.f32 [%0], {%1,%2,%3,%4};"
                 :: "l"(p), "f"(v.x), "f"(v.y), "f"(v.z), "f"(v.w) : "memory");
}
__device__ __forceinline__ __half2 h2tanh_(__half2 x){
    uint32_t r, a = *(uint32_t*)&x;
    asm("tanh.approx.f16x2 %0, %1;" : "=r"(r) : "r"(a));
    return *(__half2*)&r;
}
__device__ __forceinline__ __half2 h2ex2_(__half2 x){
    uint32_t r, a = *(uint32_t*)&x;
    asm("ex2.approx.f16x2 %0, %1;" : "=r"(r) : "r"(a));
    return *(__half2*)&r;
}
__device__ __forceinline__ float sigf(float f){
    float t;
    asm("tanh.approx.f32 %0, %1;" : "=f"(t) : "f"(0.5f * f));
    return fmaf(0.5f, t, 0.5f);
}
__device__ __forceinline__ float gact(float f, float s){
    float sp = fmaxf(s, 0.f) + __logf(1.f + __expf(-fabsf(s)));
    return sigf(f) * sp;
}

// ---- prepack ----
__global__ void pack_wbN_kernel(const float* __restrict__ Wf, const float* __restrict__ Ws){
    int idx = blockIdx.x * blockDim.x + threadIdx.x;
    if (idx >= NLAYERS*2*2*5*NPG*32) return;
    int k  = idx & 31;
    int n  = (idx >> 5) % NPG;
    int kc = (idx / (32*NPG)) % 5;
    int sp = (idx / (32*NPG*5)) & 1;
    int hf = (idx / (32*NPG*5*2)) & 1;
    int l  = idx / (32*NPG*5*2*2);
    int kg = kc*32 + k;
    float w = 0.f;
    if (n < NCOL && kg < C){
        int pl, j; colmap(n, pl, j);
        if (j < C){
            int zi = hf ? (C + kg) : kg;
            const float* W = pl ? Ws : Wf;
            w = W[(l*ZDIM + zi)*C + j];
        }
    }
    __nv_bfloat16 hi = __float2bfloat16(w);
    d_wbN[idx] = sp ? __float2bfloat16(w - __bfloat162float(hi)) : hi;
}
__global__ void pack_bph_kernel(const float* __restrict__ bf, const float* __restrict__ bs){
    int idx = blockIdx.x * blockDim.x + threadIdx.x;
    if (idx >= NLAYERS*2*NPG) return;
    int n = idx % NPG, hf = (idx / NPG) & 1, l = idx / (2*NPG);
    float v = 0.f;
    if (hf == 0 && n < NCOL){
        int pl, j; colmap(n, pl, j);
        if (j < C) v = pl ? bs[l*C + j] : bf[l*C + j];
    }
    d_bph[idx] = v;
}
__global__ void pack_w3_kernel(const float* __restrict__ Wf, const float* __restrict__ Ws){
    int idx = blockIdx.x * blockDim.x + threadIdx.x;
    if (idx >= NLAYERS*NCOL) return;
    int n = idx % NCOL, l = idx / NCOL;
    int pl, j; colmap(n, pl, j);
    float v = 0.f;
    if (j < C){ const float* W = pl ? Ws : Wf; v = W[(l*ZDIM + 258)*C + j]; }
    d_w3[idx] = v;
}
__global__ void init_x_kernel(const int* __restrict__ atoms, const float* __restrict__ pos,
                              const float* __restrict__ emb){
    int idx = blockIdx.x * blockDim.x + threadIdx.x;
    if (idx >= NROWS*XS) return;
    int n = idx / XS, c = idx - n*XS;
    float v = 0.f;
    if (n < N_NODES){
        if (c < 128) v = emb[atoms[n]*128 + c];
        else if (c == 128) v = pos[n*3 + 2];
    }
    d_xa[idx] = v;
}

// ---- CSR build + degree-ordered schedule ----
__global__ void zero_cnt_kernel(){
    int i = blockIdx.x * blockDim.x + threadIdx.x;
    if (i < N_NODES) d_cnt[i] = 0;
    if (i < 256) d_dh[i] = 0;
}
__global__ void hist_kernel(const int* __restrict__ ei){
    int e = blockIdx.x * blockDim.x + threadIdx.x;
    if (e < N_EDGES) atomicAdd(&d_cnt[ei[N_EDGES + e]], 1);
}
__global__ void scan_kernel(){
    __shared__ int wsum[32];
    __shared__ int carry;
    int tid = threadIdx.x, lane = tid & 31, wid = tid >> 5;
    if (tid == 0) carry = 0;
    __syncthreads();
    for (int base = 0; base < N_NODES; base += 1024){
        int i = base + tid;
        int v = (i < N_NODES) ? d_cnt[i] : 0;
        int x = v;
        #pragma unroll
        for (int d = 1; d < 32; d <<= 1){
            int y = __shfl_up_sync(0xffffffffu, x, d);
            if (lane >= d) x += y;
        }
        if (lane == 31) wsum[wid] = x;
        __syncthreads();
        if (wid == 0){
            int s = wsum[lane];
            #pragma unroll
            for (int d = 1; d < 32; d <<= 1){
                int y = __shfl_up_sync(0xffffffffu, s, d);
                if (lane >= d) s += y;
            }
            wsum[lane] = s;
        }
        __syncthreads();
        int excl = x - v + (wid ? wsum[wid-1] : 0) + carry;
        if (i < N_NODES){ d_rowptr[i] = excl; d_pos[i] = excl; }
        __syncthreads();
        if (tid == 0) carry += wsum[31];
        __syncthreads();
    }
    if (threadIdx.x == 0) d_rowptr[N_NODES] = carry;
}
__global__ void scatter_kernel(const int* __restrict__ ei, const float* __restrict__ pos){
    int e = blockIdx.x * blockDim.x + threadIdx.x;
    if (e >= N_EDGES) return;
    int s = ei[e], d = ei[N_EDGES + e];
    float dx = pos[s*3]-pos[d*3], dy = pos[s*3+1]-pos[d*3+1], dz = pos[s*3+2]-pos[d*3+2];
    float eav = sqrtf(dx*dx + dy*dy + dz*dz);
    int p = atomicAdd(&d_pos[d], 1);
    d_edges[p] = make_int2(s, __float_as_int(eav));
}
__global__ void dhist_kernel(){
    int n = blockIdx.x * blockDim.x + threadIdx.x;
    if (n >= N_NODES) return;
    int d = min(d_cnt[n], 255);
    atomicAdd(&d_dh[d], 1);
}
__global__ void dscan_kernel(){
    if (threadIdx.x == 0){
        int acc = 0;
        for (int d = 255; d >= 0; d--){ d_dpos[d] = acc; acc += d_dh[d]; }
    }
}
__global__ void dorder_kernel(){
    int n = blockIdx.x * blockDim.x + threadIdx.x;
    if (n >= N_NODES) return;
    int d = min(d_cnt[n], 255);
    int p = atomicAdd(&d_dpos[d], 1);
    d_order[p] = n;
}

// ---- node GEMM: both halves in one CTA (A staged once) ----
__global__ __launch_bounds__(512, 1)
void node_gemm_kernel(const float* __restrict__ xc, int layer){
    extern __shared__ __align__(16) char smem[];
    uint32_t sb = smem_u32(smem);
    int tid = threadIdx.x, lane = tid & 31, wid = tid >> 5;
    int r0 = lane >> 2, tin = lane & 3;
    int warpM = wid & 3, warpN = wid >> 2;
    int m0 = blockIdx.x * 128;

    // A stage: hi/lo bf16, row = tid>>2, quarter q = tid&3 (40 floats)
    {
        int row = tid >> 2, q = tid & 3;
        const float4* xr = (const float4*)(xc + (size_t)(m0 + row)*XS) + q*10;
        char* arow = smem + GSA + row*336 + q*80;
        #pragma unroll
        for (int j = 0; j < 10; j++){
            float4 v = xr[j];
            __nv_bfloat16 hx = __float2bfloat16(v.x), hy = __float2bfloat16(v.y);
            __nv_bfloat16 hz = __float2bfloat16(v.z), hw = __float2bfloat16(v.w);
            __nv_bfloat162 h0(hx, hy), h1(hz, hw);
            __nv_bfloat162 l0(__float2bfloat16(v.x - __bfloat162float(hx)),
                              __float2bfloat16(v.y - __bfloat162float(hy)));
            __nv_bfloat162 l1(__float2bfloat16(v.z - __bfloat162float(hz)),
                              __float2bfloat16(v.w - __bfloat162float(hw)));
            *(uint2*)(arow + j*8)        = make_uint2(*(uint32_t*)&h0, *(uint32_t*)&h1);
            *(uint2*)(arow + GSAL + j*8) = make_uint2(*(uint32_t*)&l0, *(uint32_t*)&l1);
        }
    }

    uint32_t aoff = (uint32_t)((warpM*32 + r0)*336 + tin*4);
    uint32_t boff = (uint32_t)((warpN*72 + r0)*80 + tin*4);
    float* biS = (float*)(smem + GSBI);

    for (int hf = 0; hf < 2; hf++){
        const __nv_bfloat16* wbase = d_wbN + (size_t)((layer*2 + hf)*2) * 5*NPG*32;
        // guard: previous hf's B reads complete before overwriting buffers
        __syncthreads();
        #pragma unroll
        for (int pc = 0; pc < 2; pc++){
            for (int i = tid; i < 2304; i += 512){
                int sp = i / 1152, rr = i % 1152, n = rr >> 2, kv = rr & 3;
                const void* g = wbase + ((size_t)sp*5 + pc)*NPG*32 + n*32 + kv*8;
                cpasync16(sb + GSB + pc*GSBUF + sp*GSSP + n*80 + kv*16, g);
            }
            asm volatile("cp.async.commit_group;" ::: "memory");
        }
        for (int i = tid; i < NPG; i += 512) biS[i] = d_bph[(layer*2 + hf)*NPG + i];

        float acc[2][9][4];
        #pragma unroll
        for (int a = 0; a < 2; a++)
            #pragma unroll
            for (int b = 0; b < 9; b++)
                #pragma unroll
                for (int c = 0; c < 4; c++) acc[a][b][c] = 0.f;

        for (int sc = 0; sc < 5; sc++){
            int buf = sc & 1;
            if (sc == 4) asm volatile("cp.async.wait_group 0;" ::: "memory");
            else         asm volatile("cp.async.wait_group 1;" ::: "memory");
            __syncthreads();
            const char* bbuf = smem + GSB + buf*GSBUF;
            #pragma unroll
            for (int ks = 0; ks < 2; ks++){
                uint32_t ka = (uint32_t)(sc*32 + ks*16)*2;
                const char* ap = smem + GSA + aoff + ka;
                uint32_t ah[2][4], al[2][4];
                #pragma unroll
                for (int mt = 0; mt < 2; mt++){
                    const char* p = ap + mt*5376;
                    ah[mt][0] = *(const uint32_t*)(p);
                    ah[mt][1] = *(const uint32_t*)(p + 2688);
                    ah[mt][2] = *(const uint32_t*)(p + 16);
                    ah[mt][3] = *(const uint32_t*)(p + 2704);
                    const char* q = p + GSAL;
                    al[mt][0] = *(const uint32_t*)(q);
                    al[mt][1] = *(const uint32_t*)(q + 2688);
                    al[mt][2] = *(const uint32_t*)(q + 16);
                    al[mt][3] = *(const uint32_t*)(q + 2704);
                }
                uint32_t kb = (uint32_t)ks*32;
                #pragma unroll
                for (int nt = 0; nt < 9; nt++){
                    const char* bp = bbuf + boff + nt*640 + kb;
                    uint32_t bh0 = *(const uint32_t*)(bp);
                    uint32_t bh1 = *(const uint32_t*)(bp + 16);
                    uint32_t bl0 = *(const uint32_t*)(bp + GSSP);
                    uint32_t bl1 = *(const uint32_t*)(bp + GSSP + 16);
                    mma16816(acc[0][nt], ah[0][0], ah[0][1], ah[0][2], ah[0][3], bh0, bh1);
                    mma16816(acc[1][nt], ah[1][0], ah[1][1], ah[1][2], ah[1][3], bh0, bh1);
                    mma16816(acc[0][nt], al[0][0], al[0][1], al[0][2], al[0][3], bh0, bh1);
                    mma16816(acc[1][nt], al[1][0], al[1][1], al[1][2], al[1][3], bh0, bh1);
                    mma16816(acc[0][nt], ah[0][0], ah[0][1], ah[0][2], ah[0][3], bl0, bl1);
                    mma16816(acc[1][nt], ah[1][0], ah[1][1], ah[1][2], ah[1][3], bl0, bl1);
                }
            }
            __syncthreads();
            if (sc < 3){
                int nc = sc + 2;
                for (int i = tid; i < 2304; i += 512){
                    int sp = i / 1152, rr = i % 1152, n = rr >> 2, kv = rr & 3;
                    const void* g = wbase + ((size_t)sp*5 + nc)*NPG*32 + n*32 + kv*8;
                    cpasync16(sb + GSB + buf*GSBUF + sp*GSSP + n*80 + kv*16, g);
                }
                asm volatile("cp.async.commit_group;" ::: "memory");
            }
        }

        #pragma unroll
        for (int mt = 0; mt < 2; mt++){
            #pragma unroll
            for (int nt = 0; nt < 9; nt++){
                int col = warpN*72 + nt*8 + tin*2;
                if (col >= NCOL) continue;
                float b0 = biS[col], b1 = biS[col + 1];
                #pragma unroll
                for (int h = 0; h < 2; h++){
                    int row = m0 + warpM*32 + mt*16 + r0 + h*8;
                    float v0 = acc[mt][nt][2*h] + b0;
                    float v1 = acc[mt][nt][2*h+1] + b1;
                    if (hf == 0){
                        *(float2*)(d_P1 + (size_t)row*NCOL + col) = make_float2(v0, v1);
                    } else {
                        *(__half2*)(d_P2h + (size_t)row*P2S + col) = __floats2half2_rn(v0, v1);
                    }
                }
            }
        }
    }
}

// ---- edge phase: warp-per-node, software-pipelined gather, f16x2 transcendentals ----
__global__ __launch_bounds__(256)
void edge_csr_kernel(const float* __restrict__ xc, float* __restrict__ xn, int layer){
    int lane = threadIdx.x & 31, warp = threadIdx.x >> 5;
    int n = d_order[blockIdx.x * 8 + warp];
    int cb = lane * 8;
    const float* w3 = d_w3 + layer * NCOL;
    const float* p1 = d_P1 + (size_t)n * NCOL;
    float4 pa = *(const float4*)(p1 + cb);
    float4 pb = *(const float4*)(p1 + cb + 4);
    float4 wa = *(const float4*)(w3 + cb);
    float4 wb = *(const float4*)(w3 + cb + 4);
    float f1h0=0.5f*pa.x, f1h1=0.5f*pa.y, f1h2=0.5f*pb.x, f1h3=0.5f*pb.y;
    float wfh0=0.5f*wa.x, wfh1=0.5f*wa.y, wfh2=0.5f*wb.x, wfh3=0.5f*wb.y;
    float s10=pa.z, s11=pa.w, s12=pb.z, s13=pb.w;
    float ws0=wa.z, ws1=wa.w, ws2=wb.z, ws3=wb.w;
    float f1t=0.f, s1t=0.f, wft=0.f, wst=0.f;
    if (lane == 0){ f1t=p1[256]; s1t=p1[258]; wft=w3[256]; wst=w3[258]; }
    const __half2 h05 = __float2half2_rn(0.5f);
    int beg = d_rowptr[n], end = d_rowptr[n + 1];
    float a0=0.f, a1=0.f, a2=0.f, a3=0.f, at=0.f;

    int2 e = make_int2(0, 0);
    uint4 w = make_uint4(0, 0, 0, 0);
    uint2 tw = make_uint2(0, 0);
    if (beg < end){
        e = d_edges[beg];
        const __half* q = d_P2h + (size_t)e.x * P2S;
        w = *(const uint4*)(q + cb);
        if (lane == 0) tw = *(const uint2*)(q + 256);
    }
    for (int i = beg; i < end; i++){
        // prefetch next edge's gather before computing this one
        int2 en = e;
        uint4 wn = w;
        uint2 twn = tw;
        if (i + 1 < end){
            en = d_edges[i + 1];
            const __half* qn = d_P2h + (size_t)en.x * P2S;
            wn = *(const uint4*)(qn + cb);
            if (lane == 0) twn = *(const uint2*)(qn + 256);
        }
        float ev = __int_as_float(e.y);
        __half2 cfA = __floats2half2_rn(fmaf(ev, wfh0, f1h0), fmaf(ev, wfh1, f1h1));
        __half2 cfB = __floats2half2_rn(fmaf(ev, wfh2, f1h2), fmaf(ev, wfh3, f1h3));
        float2 t01 = __half22float2(h2tanh_(__hfma2(*(__half2*)&w.x, h05, cfA)));
        float2 t23 = __half22float2(h2tanh_(__hfma2(*(__half2*)&w.z, h05, cfB)));
        float2 sy = __half22float2(*(__half2*)&w.y);
        float2 sw2 = __half22float2(*(__half2*)&w.w);
        float s0 = fmaf(ev, ws0, s10) + sy.x;
        float s1 = fmaf(ev, ws1, s11) + sy.y;
        float s2 = fmaf(ev, ws2, s12) + sw2.x;
        float s3 = fmaf(ev, ws3, s13) + sw2.y;
        __half2 uiA = __floats2half2_rn(fabsf(s0)*-1.44269504f, fabsf(s1)*-1.44269504f);
        __half2 uiB = __floats2half2_rn(fabsf(s2)*-1.44269504f, fabsf(s3)*-1.44269504f);
        float2 u01 = __half22float2(h2ex2_(uiA));
        float2 u23 = __half22float2(h2ex2_(uiB));
        float sp0 = fmaxf(s0, 0.f) + __logf(1.f + u01.x);
        float sp1 = fmaxf(s1, 0.f) + __logf(1.f + u01.y);
        float sp2 = fmaxf(s2, 0.f) + __logf(1.f + u23.x);
        float sp3 = fmaxf(s3, 0.f) + __logf(1.f + u23.y);
        a0 = fmaf(fmaf(0.5f, t01.x, 0.5f), sp0, a0);
        a1 = fmaf(fmaf(0.5f, t01.y, 0.5f), sp1, a1);
        a2 = fmaf(fmaf(0.5f, t23.x, 0.5f), sp2, a2);
        a3 = fmaf(fmaf(0.5f, t23.y, 0.5f), sp3, a3);
        if (lane == 0){
            float2 tf = __half22float2(*(__half2*)&tw.x);
            float2 ts = __half22float2(*(__half2*)&tw.y);
            at += gact(f1t + tf.x + ev*wft, s1t + ts.x + ev*wst);
        }
        e = en; w = wn; tw = twn;
    }

    float* xr = xn + (size_t)n * XS;
    const float* xcr = xc + (size_t)n * XS;
    float4 xv = *(const float4*)(xcr + lane*4);
    xv.x += a0; xv.y += a1; xv.z += a2; xv.w += a3;
    *(float4*)(xr + lane*4) = xv;
    if (lane == 0) xr[128] = xcr[128] + at;
}

// ---- pooling + head ----
__global__ void zero_pool_kernel(){
    int idx = blockIdx.x * blockDim.x + threadIdx.x;
    if (idx < NUM_GRAPHS*PLN) d_gsum[idx] = 0.f;
    if (idx < NUM_GRAPHS)     d_gcnt[idx] = 0.f;
}
__global__ __launch_bounds__(256)
void pool_kernel(const float* __restrict__ x, const int* __restrict__ batch){
    int lane = threadIdx.x & 31, warp = threadIdx.x >> 5;
    int n = blockIdx.x * 8 + warp;
    int b = batch[n];
    const float* xr = x + (size_t)n * XS;
    float4 v = *(const float4*)(xr + lane*4);
    red4(&d_gsum[b*PLN + lane*4], v);
    if (lane == 0) atomicAdd(&d_gsum[b*PLN + 128], xr[128]);
    if (lane == 1) atomicAdd(&d_gcnt[b], 1.f);
}
__global__ void head_kernel(const float* __restrict__ Wfc, const float* __restrict__ bfc,
                            const float* __restrict__ Wout, const float* __restrict__ bout,
                            float* __restrict__ out){
    int g = blockIdx.x, t = threadIdx.x;
    __shared__ float row[C];
    __shared__ float red[256];
    if (t < C) row[t] = d_gsum[g*PLN + t] / fmaxf(d_gcnt[g], 1.f);
    __syncthreads();
    for (int l = 0; l < 3; l++){
        float y = 0.f;
        if (t < C){
            #pragma unroll 4
            for (int k = 0; k < C; k++) y = fmaf(row[k], Wfc[(l*C + k)*C + t], y);
            y += bfc[l*C + t];
        }
        __syncthreads();
        if (t < C) row[t] = y;
        __syncthreads();
    }
    red[t] = (t < C) ? row[t]*Wout[t] : 0.f;
    __syncthreads();
    for (int s = 128; s > 0; s >>= 1){ if (t < s) red[t] += red[t + s]; __syncthreads(); }
    if (t == 0) out[g] = red[0] + bout[0];
}

extern "C" void kernel_launch(void* const* d_in, const int* in_sizes, int n_in,
                              void* d_out, int out_size){
    const int*   atoms = (const int*)d_in[0];
    const float* pos   = (const float*)d_in[1];
    const int*   ei    = (const int*)d_in[2];
    const int*   batch = (const int*)d_in[3];
    const float* emb   = (const float*)d_in[4];
    const float* Wf    = (const float*)d_in[5];
    const float* bf    = (const float*)d_in[6];
    const float* Ws    = (const float*)d_in[7];
    const float* bs    = (const float*)d_in[8];
    const float* Wfc   = (const float*)d_in[9];
    const float* bfc   = (const float*)d_in[10];
    const float* Wout  = (const float*)d_in[11];
    const float* bout  = (const float*)d_in[12];
    float* out = (float*)d_out;

    cudaFuncSetAttribute(node_gemm_kernel,
                         cudaFuncAttributeMaxDynamicSharedMemorySize, GSMEM);

    float *xa, *xb;
    cudaGetSymbolAddress((void**)&xa, d_xa);
    cudaGetSymbolAddress((void**)&xb, d_xb);

    pack_wbN_kernel<<<(NLAYERS*2*2*5*NPG*32 + 255)/256, 256>>>(Wf, Ws);
    pack_bph_kernel<<<(NLAYERS*2*NPG + 255)/256, 256>>>(bf, bs);
    pack_w3_kernel<<<(NLAYERS*NCOL + 255)/256, 256>>>(Wf, Ws);
    init_x_kernel<<<(NROWS*XS + 255)/256, 256>>>(atoms, pos, emb);

    zero_cnt_kernel<<<(N_NODES + 255)/256, 256>>>();
    hist_kernel<<<(N_EDGES + 255)/256, 256>>>(ei);
    scan_kernel<<<1, 1024>>>();
    scatter_kernel<<<(N_EDGES + 255)/256, 256>>>(ei, pos);
    dhist_kernel<<<(N_NODES + 255)/256, 256>>>();
    dscan_kernel<<<1, 32>>>();
    dorder_kernel<<<(N_NODES + 255)/256, 256>>>();

    float* cur = xa;
    float* nxt = xb;
    for (int l = 0; l < NLAYERS; l++){
        node_gemm_kernel<<<NROWS/128, 512, GSMEM>>>(cur, l);
        edge_csr_kernel<<<N_NODES/8, 256>>>(cur, nxt, l);
        float* tmp = cur; cur = nxt; nxt = tmp;
    }

    zero_pool_kernel<<<(NUM_GRAPHS*PLN + 255)/256, 256>>>();
    pool_kernel<<<N_NODES/8, 256>>>(cur, batch);
    head_kernel<<<NUM_GRAPHS, 256>>>(Wfc, bfc, Wout, bout, out);
}

// round 12
// speedup vs baseline: 1.1241x; 1.1241x over previous
#include <cuda_runtime.h>
#include <cuda_bf16.h>
#include <cuda_fp16.h>
#include <cstdint>
#include <math.h>

#define N_NODES   50000
#define NROWS     50048
#define N_EDGES   800000
#define NUM_GRAPHS 256
#define C         129
#define ZDIM      259
#define NLAYERS   5
#define XS        160
#define PLN       132
#define NCOL      264
#define NPG       288
#define P2S       320

// GEMM smem offsets
#define GSA    0
#define GSAL   43008
#define GSB    86016
#define GSSP   23040
#define GSBUF  46080
#define GSBI   178176
#define GSMEM  179328

__device__ __align__(16) __nv_bfloat16 d_wbN[NLAYERS*2*2*5*NPG*32];
__device__ float d_bph[NLAYERS*2*NPG];
__device__ float d_w3[NLAYERS*NCOL];
__device__ __align__(16) float d_xa[NROWS*XS];
__device__ __align__(16) float d_xb[NROWS*XS];
__device__ __align__(16) float  d_P1[(size_t)NROWS*NCOL];
__device__ __align__(16) __half d_P2h[(size_t)NROWS*P2S];
__device__ int   d_cnt[N_NODES];
__device__ int   d_rowptr[N_NODES + 1];
__device__ int   d_pos[N_NODES];
__device__ __align__(8) int2 d_edges[N_EDGES];
__device__ int   d_edst[N_EDGES];
__device__ int   d_dh[256];
__device__ int   d_dpos[256];
__device__ int   d_order[N_NODES];
__device__ float d_gsum[NUM_GRAPHS*PLN];
__device__ float d_gcnt[NUM_GRAPHS];

__device__ __host__ __forceinline__ void colmap(int n, int& pl, int& j){
    pl = (n >> 1) & 1;
    j  = 2*(n >> 2) + (n & 1);
}

__device__ __forceinline__ uint32_t smem_u32(const void* p){
    uint32_t a;
    asm("{ .reg .u64 t; cvta.to.shared.u64 t, %1; cvt.u32.u64 %0, t; }" : "=r"(a) : "l"(p));
    return a;
}
__device__ __forceinline__ void mma16816(float* d, uint32_t a0, uint32_t a1,
                                         uint32_t a2, uint32_t a3,
                                         uint32_t b0, uint32_t b1){
    asm volatile(
        "mma.sync.aligned.m16n8k16.row.col.f32.bf16.bf16.f32 "
        "{%0,%1,%2,%3}, {%4,%5,%6,%7}, {%8,%9}, {%0,%1,%2,%3};"
        : "+f"(d[0]), "+f"(d[1]), "+f"(d[2]), "+f"(d[3])
        : "r"(a0), "r"(a1), "r"(a2), "r"(a3), "r"(b0), "r"(b1));
}
__device__ __forceinline__ void cpasync16(uint32_t s, const void* g){
    asm volatile("cp.async.cg.shared.global [%0], [%1], 16;" :: "r"(s), "l"(g));
}
__device__ __forceinline__ void red4(float* p, float4 v){
    asm volatile("red.global.add.v4.f32 [%0], {%1,%2,%3,%4};"
                 :: "l"(p), "f"(v.x), "f"(v.y), "f"(v.z), "f"(v.w) : "memory");
}
__device__ __forceinline__ __half2 h2tanh_(__half2 x){
    uint32_t r, a = *(uint32_t*)&x;
    asm("tanh.approx.f16x2 %0, %1;" : "=r"(r) : "r"(a));
    return *(__half2*)&r;
}
__device__ __forceinline__ __half2 h2ex2_(__half2 x){
    uint32_t r, a = *(uint32_t*)&x;
    asm("ex2.approx.f16x2 %0, %1;" : "=r"(r) : "r"(a));
    return *(__half2*)&r;
}
__device__ __forceinline__ float lg2f_(float x){
    float r;
    asm("lg2.approx.f32 %0, %1;" : "=f"(r) : "f"(x));
    return r;
}
__device__ __forceinline__ float sigf(float f){
    float t;
    asm("tanh.approx.f32 %0, %1;" : "=f"(t) : "f"(0.5f * f));
    return fmaf(0.5f, t, 0.5f);
}
__device__ __forceinline__ float gact(float f, float s){
    float sp = fmaxf(s, 0.f) + __logf(1.f + __expf(-fabsf(s)));
    return sigf(f) * sp;
}

// ---- prepack ----
__global__ void pack_wbN_kernel(const float* __restrict__ Wf, const float* __restrict__ Ws){
    int idx = blockIdx.x * blockDim.x + threadIdx.x;
    if (idx >= NLAYERS*2*2*5*NPG*32) return;
    int k  = idx & 31;
    int n  = (idx >> 5) % NPG;
    int kc = (idx / (32*NPG)) % 5;
    int sp = (idx / (32*NPG*5)) & 1;
    int hf = (idx / (32*NPG*5*2)) & 1;
    int l  = idx / (32*NPG*5*2*2);
    int kg = kc*32 + k;
    float w = 0.f;
    if (n < NCOL && kg < C){
        int pl, j; colmap(n, pl, j);
        if (j < C){
            int zi = hf ? (C + kg) : kg;
            const float* W = pl ? Ws : Wf;
            w = W[(l*ZDIM + zi)*C + j];
        }
    }
    __nv_bfloat16 hi = __float2bfloat16(w);
    d_wbN[idx] = sp ? __float2bfloat16(w - __bfloat162float(hi)) : hi;
}
__global__ void pack_bph_kernel(const float* __restrict__ bf, const float* __restrict__ bs){
    int idx = blockIdx.x * blockDim.x + threadIdx.x;
    if (idx >= NLAYERS*2*NPG) return;
    int n = idx % NPG, hf = (idx / NPG) & 1, l = idx / (2*NPG);
    float v = 0.f;
    if (hf == 0 && n < NCOL){
        int pl, j; colmap(n, pl, j);
        if (j < C) v = pl ? bs[l*C + j] : bf[l*C + j];
    }
    d_bph[idx] = v;
}
__global__ void pack_w3_kernel(const float* __restrict__ Wf, const float* __restrict__ Ws){
    int idx = blockIdx.x * blockDim.x + threadIdx.x;
    if (idx >= NLAYERS*NCOL) return;
    int n = idx % NCOL, l = idx / NCOL;
    int pl, j; colmap(n, pl, j);
    float v = 0.f;
    if (j < C){ const float* W = pl ? Ws : Wf; v = W[(l*ZDIM + 258)*C + j]; }
    d_w3[idx] = v;
}
__global__ void init_x_kernel(const int* __restrict__ atoms, const float* __restrict__ pos,
                              const float* __restrict__ emb){
    int idx = blockIdx.x * blockDim.x + threadIdx.x;
    if (idx >= NROWS*XS) return;
    int n = idx / XS, c = idx - n*XS;
    float v = 0.f;
    if (n < N_NODES){
        if (c < 128) v = emb[atoms[n]*128 + c];
        else if (c == 128) v = pos[n*3 + 2];
    }
    d_xa[idx] = v;
}

// ---- CSR build + degree-ordered schedule ----
__global__ void zero_cnt_kernel(){
    int i = blockIdx.x * blockDim.x + threadIdx.x;
    if (i < N_NODES) d_cnt[i] = 0;
    if (i < 256) d_dh[i] = 0;
}
__global__ void hist_kernel(const int* __restrict__ ei){
    int e = blockIdx.x * blockDim.x + threadIdx.x;
    if (e < N_EDGES) atomicAdd(&d_cnt[ei[N_EDGES + e]], 1);
}
__global__ void scan_kernel(){
    __shared__ int wsum[32];
    __shared__ int carry;
    int tid = threadIdx.x, lane = tid & 31, wid = tid >> 5;
    if (tid == 0) carry = 0;
    __syncthreads();
    for (int base = 0; base < N_NODES; base += 1024){
        int i = base + tid;
        int v = (i < N_NODES) ? d_cnt[i] : 0;
        int x = v;
        #pragma unroll
        for (int d = 1; d < 32; d <<= 1){
            int y = __shfl_up_sync(0xffffffffu, x, d);
            if (lane >= d) x += y;
        }
        if (lane == 31) wsum[wid] = x;
        __syncthreads();
        if (wid == 0){
            int s = wsum[lane];
            #pragma unroll
            for (int d = 1; d < 32; d <<= 1){
                int y = __shfl_up_sync(0xffffffffu, s, d);
                if (lane >= d) s += y;
            }
            wsum[lane] = s;
        }
        __syncthreads();
        int excl = x - v + (wid ? wsum[wid-1] : 0) + carry;
        if (i < N_NODES){ d_rowptr[i] = excl; d_pos[i] = excl; }
        __syncthreads();
        if (tid == 0) carry += wsum[31];
        __syncthreads();
    }
    if (threadIdx.x == 0) d_rowptr[N_NODES] = carry;
}
__global__ void scatter_kernel(const int* __restrict__ ei, const float* __restrict__ pos){
    int e = blockIdx.x * blockDim.x + threadIdx.x;
    if (e >= N_EDGES) return;
    int s = ei[e], d = ei[N_EDGES + e];
    float dx = pos[s*3]-pos[d*3], dy = pos[s*3+1]-pos[d*3+1], dz = pos[s*3+2]-pos[d*3+2];
    float eav = sqrtf(dx*dx + dy*dy + dz*dz);
    int p = atomicAdd(&d_pos[d], 1);
    d_edges[p] = make_int2(s, __float_as_int(eav));
    d_edst[p] = d;
}
__global__ void dhist_kernel(){
    int n = blockIdx.x * blockDim.x + threadIdx.x;
    if (n >= N_NODES) return;
    int d = min(d_cnt[n], 255);
    atomicAdd(&d_dh[d], 1);
}
__global__ void dscan_kernel(){
    if (threadIdx.x == 0){
        int acc = 0;
        for (int d = 255; d >= 0; d--){ d_dpos[d] = acc; acc += d_dh[d]; }
    }
}
__global__ void dorder_kernel(){
    int n = blockIdx.x * blockDim.x + threadIdx.x;
    if (n >= N_NODES) return;
    int d = min(d_cnt[n], 255);
    int p = atomicAdd(&d_dpos[d], 1);
    d_order[p] = n;
}

// ---- node GEMM: both halves in one CTA (A staged once) ----
__global__ __launch_bounds__(512, 1)
void node_gemm_kernel(const float* __restrict__ xc, int layer){
    extern __shared__ __align__(16) char smem[];
    uint32_t sb = smem_u32(smem);
    int tid = threadIdx.x, lane = tid & 31, wid = tid >> 5;
    int r0 = lane >> 2, tin = lane & 3;
    int warpM = wid & 3, warpN = wid >> 2;
    int m0 = blockIdx.x * 128;

    {
        int row = tid >> 2, q = tid & 3;
        const float4* xr = (const float4*)(xc + (size_t)(m0 + row)*XS) + q*10;
        char* arow = smem + GSA + row*336 + q*80;
        #pragma unroll
        for (int j = 0; j < 10; j++){
            float4 v = xr[j];
            __nv_bfloat16 hx = __float2bfloat16(v.x), hy = __float2bfloat16(v.y);
            __nv_bfloat16 hz = __float2bfloat16(v.z), hw = __float2bfloat16(v.w);
            __nv_bfloat162 h0(hx, hy), h1(hz, hw);
            __nv_bfloat162 l0(__float2bfloat16(v.x - __bfloat162float(hx)),
                              __float2bfloat16(v.y - __bfloat162float(hy)));
            __nv_bfloat162 l1(__float2bfloat16(v.z - __bfloat162float(hz)),
                              __float2bfloat16(v.w - __bfloat162float(hw)));
            *(uint2*)(arow + j*8)        = make_uint2(*(uint32_t*)&h0, *(uint32_t*)&h1);
            *(uint2*)(arow + GSAL + j*8) = make_uint2(*(uint32_t*)&l0, *(uint32_t*)&l1);
        }
    }

    uint32_t aoff = (uint32_t)((warpM*32 + r0)*336 + tin*4);
    uint32_t boff = (uint32_t)((warpN*72 + r0)*80 + tin*4);
    float* biS = (float*)(smem + GSBI);

    for (int hf = 0; hf < 2; hf++){
        const __nv_bfloat16* wbase = d_wbN + (size_t)((layer*2 + hf)*2) * 5*NPG*32;
        __syncthreads();
        #pragma unroll
        for (int pc = 0; pc < 2; pc++){
            for (int i = tid; i < 2304; i += 512){
                int sp = i / 1152, rr = i % 1152, n = rr >> 2, kv = rr & 3;
                const void* g = wbase + ((size_t)sp*5 + pc)*NPG*32 + n*32 + kv*8;
                cpasync16(sb + GSB + pc*GSBUF + sp*GSSP + n*80 + kv*16, g);
            }
            asm volatile("cp.async.commit_group;" ::: "memory");
        }
        for (int i = tid; i < NPG; i += 512) biS[i] = d_bph[(layer*2 + hf)*NPG + i];

        float acc[2][9][4];
        #pragma unroll
        for (int a = 0; a < 2; a++)
            #pragma unroll
            for (int b = 0; b < 9; b++)
                #pragma unroll
                for (int c = 0; c < 4; c++) acc[a][b][c] = 0.f;

        for (int sc = 0; sc < 5; sc++){
            int buf = sc & 1;
            if (sc == 4) asm volatile("cp.async.wait_group 0;" ::: "memory");
            else         asm volatile("cp.async.wait_group 1;" ::: "memory");
            __syncthreads();
            const char* bbuf = smem + GSB + buf*GSBUF;
            #pragma unroll
            for (int ks = 0; ks < 2; ks++){
                uint32_t ka = (uint32_t)(sc*32 + ks*16)*2;
                const char* ap = smem + GSA + aoff + ka;
                uint32_t ah[2][4], al[2][4];
                #pragma unroll
                for (int mt = 0; mt < 2; mt++){
                    const char* p = ap + mt*5376;
                    ah[mt][0] = *(const uint32_t*)(p);
                    ah[mt][1] = *(const uint32_t*)(p + 2688);
                    ah[mt][2] = *(const uint32_t*)(p + 16);
                    ah[mt][3] = *(const uint32_t*)(p + 2704);
                    const char* q = p + GSAL;
                    al[mt][0] = *(const uint32_t*)(q);
                    al[mt][1] = *(const uint32_t*)(q + 2688);
                    al[mt][2] = *(const uint32_t*)(q + 16);
                    al[mt][3] = *(const uint32_t*)(q + 2704);
                }
                uint32_t kb = (uint32_t)ks*32;
                #pragma unroll
                for (int nt = 0; nt < 9; nt++){
                    const char* bp = bbuf + boff + nt*640 + kb;
                    uint32_t bh0 = *(const uint32_t*)(bp);
                    uint32_t bh1 = *(const uint32_t*)(bp + 16);
                    uint32_t bl0 = *(const uint32_t*)(bp + GSSP);
                    uint32_t bl1 = *(const uint32_t*)(bp + GSSP + 16);
                    mma16816(acc[0][nt], ah[0][0], ah[0][1], ah[0][2], ah[0][3], bh0, bh1);
                    mma16816(acc[1][nt], ah[1][0], ah[1][1], ah[1][2], ah[1][3], bh0, bh1);
                    mma16816(acc[0][nt], al[0][0], al[0][1], al[0][2], al[0][3], bh0, bh1);
                    mma16816(acc[1][nt], al[1][0], al[1][1], al[1][2], al[1][3], bh0, bh1);
                    mma16816(acc[0][nt], ah[0][0], ah[0][1], ah[0][2], ah[0][3], bl0, bl1);
                    mma16816(acc[1][nt], ah[1][0], ah[1][1], ah[1][2], ah[1][3], bl0, bl1);
                }
            }
            __syncthreads();
            if (sc < 3){
                int nc = sc + 2;
                for (int i = tid; i < 2304; i += 512){
                    int sp = i / 1152, rr = i % 1152, n = rr >> 2, kv = rr & 3;
                    const void* g = wbase + ((size_t)sp*5 + nc)*NPG*32 + n*32 + kv*8;
                    cpasync16(sb + GSB + buf*GSBUF + sp*GSSP + n*80 + kv*16, g);
                }
                asm volatile("cp.async.commit_group;" ::: "memory");
            }
        }

        #pragma unroll
        for (int mt = 0; mt < 2; mt++){
            #pragma unroll
            for (int nt = 0; nt < 9; nt++){
                int col = warpN*72 + nt*8 + tin*2;
                if (col >= NCOL) continue;
                float b0 = biS[col], b1 = biS[col + 1];
                #pragma unroll
                for (int h = 0; h < 2; h++){
                    int row = m0 + warpM*32 + mt*16 + r0 + h*8;
                    float v0 = acc[mt][nt][2*h] + b0;
                    float v1 = acc[mt][nt][2*h+1] + b1;
                    if (hf == 0){
                        *(float2*)(d_P1 + (size_t)row*NCOL + col) = make_float2(v0, v1);
                    } else {
                        *(__half2*)(d_P2h + (size_t)row*P2S + col) = __floats2half2_rn(v0, v1);
                    }
                }
            }
        }
    }
}

// ---- edge phase: warp-per-node, lean branch-free loop (channels 0..127) ----
__global__ __launch_bounds__(256)
void edge_csr_kernel(const float* __restrict__ xc, float* __restrict__ xn, int layer){
    int lane = threadIdx.x & 31, warp = threadIdx.x >> 5;
    int n = d_order[blockIdx.x * 8 + warp];
    int cb = lane * 8;
    const float* w3 = d_w3 + layer * NCOL;
    const float* p1 = d_P1 + (size_t)n * NCOL;
    float4 pa = *(const float4*)(p1 + cb);
    float4 pb = *(const float4*)(p1 + cb + 4);
    float4 wa = *(const float4*)(w3 + cb);
    float4 wb = *(const float4*)(w3 + cb + 4);
    // half2 constants for the F (gate) plane, pre-scaled by 0.5
    __half2 f1hA = __floats2half2_rn(0.5f*pa.x, 0.5f*pa.y);
    __half2 f1hB = __floats2half2_rn(0.5f*pb.x, 0.5f*pb.y);
    __half2 wfhA = __floats2half2_rn(0.5f*wa.x, 0.5f*wa.y);
    __half2 wfhB = __floats2half2_rn(0.5f*wb.x, 0.5f*wb.y);
    float s10=pa.z, s11=pa.w, s12=pb.z, s13=pb.w;
    float ws0=wa.z, ws1=wa.w, ws2=wb.z, ws3=wb.w;
    const __half2 h05 = __float2half2_rn(0.5f);
    const __half2 h1  = __float2half2_rn(1.0f);
    int beg = d_rowptr[n], end = d_rowptr[n + 1];
    float a0=0.f, a1=0.f, a2=0.f, a3=0.f;

    #pragma unroll 2
    for (int i = beg; i < end; i++){
        int2 e = d_edges[i];
        float ev = __int_as_float(e.y);
        const __half* q = d_P2h + (size_t)e.x * P2S;
        uint4 w = *(const uint4*)(q + cb);
        __half2 evh = __float2half2_rn(ev);
        // gate: t = tanh(0.5*(f1 + f2 + ev*wf))
        __half2 inA = __hfma2(*(__half2*)&w.x, h05, __hfma2(evh, wfhA, f1hA));
        __half2 inB = __hfma2(*(__half2*)&w.z, h05, __hfma2(evh, wfhB, f1hB));
        __half2 tA = h2tanh_(inA);
        __half2 tB = h2tanh_(inB);
        // s plane in f32
        float2 sy = __half22float2(*(__half2*)&w.y);
        float2 sw = __half22float2(*(__half2*)&w.w);
        float s0 = fmaf(ev, ws0, s10) + sy.x;
        float s1 = fmaf(ev, ws1, s11) + sy.y;
        float s2 = fmaf(ev, ws2, s12) + sw.x;
        float s3 = fmaf(ev, ws3, s13) + sw.y;
        // softplus: max(s,0) + ln2*lg2(1 + 2^(-|s|*log2e))
        __half2 uiA = __floats2half2_rn(fabsf(s0)*-1.44269504f, fabsf(s1)*-1.44269504f);
        __half2 uiB = __floats2half2_rn(fabsf(s2)*-1.44269504f, fabsf(s3)*-1.44269504f);
        float2 u01 = __half22float2(h2ex2_(uiA));
        float2 u23 = __half22float2(h2ex2_(uiB));
        float sp0 = fmaf(0.69314718f, lg2f_(1.f + u01.x), fmaxf(s0, 0.f));
        float sp1 = fmaf(0.69314718f, lg2f_(1.f + u01.y), fmaxf(s1, 0.f));
        float sp2 = fmaf(0.69314718f, lg2f_(1.f + u23.x), fmaxf(s2, 0.f));
        float sp3 = fmaf(0.69314718f, lg2f_(1.f + u23.y), fmaxf(s3, 0.f));
        // accumulate (1+t)*sp ; final 0.5 applied at writeback
        float2 tp01 = __half22float2(__hadd2(tA, h1));
        float2 tp23 = __half22float2(__hadd2(tB, h1));
        a0 = fmaf(tp01.x, sp0, a0);
        a1 = fmaf(tp01.y, sp1, a1);
        a2 = fmaf(tp23.x, sp2, a2);
        a3 = fmaf(tp23.y, sp3, a3);
    }

    float* xr = xn + (size_t)n * XS;
    const float* xcr = xc + (size_t)n * XS;
    float4 xv = *(const float4*)(xcr + lane*4);
    xv.x = fmaf(0.5f, a0, xv.x);
    xv.y = fmaf(0.5f, a1, xv.y);
    xv.z = fmaf(0.5f, a2, xv.z);
    xv.w = fmaf(0.5f, a3, xv.w);
    *(float4*)(xr + lane*4) = xv;
    if (lane == 0) xr[128] = xcr[128];   // residual base; tail kernel adds messages
}

// ---- tail channel (128): one thread per edge, atomic accumulate ----
__global__ __launch_bounds__(256)
void edge_tail_kernel(float* __restrict__ xn, int layer){
    int e = blockIdx.x * 256 + threadIdx.x;
    int2 ed = d_edges[e];
    int dst = d_edst[e];
    float ev = __int_as_float(ed.y);
    const __half* q = d_P2h + (size_t)ed.x * P2S;
    uint2 tw = *(const uint2*)(q + 256);
    float4 pt = *(const float4*)(d_P1 + (size_t)dst*NCOL + 256);
    float wf = d_w3[layer*NCOL + 256];
    float ws = d_w3[layer*NCOL + 258];
    float2 tf = __half22float2(*(__half2*)&tw.x);
    float2 ts = __half22float2(*(__half2*)&tw.y);
    float m = gact(pt.x + tf.x + ev*wf, pt.z + ts.x + ev*ws);
    atomicAdd(xn + (size_t)dst*XS + 128, m);
}

// ---- pooling + head ----
__global__ void zero_pool_kernel(){
    int idx = blockIdx.x * blockDim.x + threadIdx.x;
    if (idx < NUM_GRAPHS*PLN) d_gsum[idx] = 0.f;
    if (idx < NUM_GRAPHS)     d_gcnt[idx] = 0.f;
}
__global__ __launch_bounds__(256)
void pool_kernel(const float* __restrict__ x, const int* __restrict__ batch){
    int lane = threadIdx.x & 31, warp = threadIdx.x >> 5;
    int n = blockIdx.x * 8 + warp;
    int b = batch[n];
    const float* xr = x + (size_t)n * XS;
    float4 v = *(const float4*)(xr + lane*4);
    red4(&d_gsum[b*PLN + lane*4], v);
    if (lane == 0) atomicAdd(&d_gsum[b*PLN + 128], xr[128]);
    if (lane == 1) atomicAdd(&d_gcnt[b], 1.f);
}
__global__ void head_kernel(const float* __restrict__ Wfc, const float* __restrict__ bfc,
                            const float* __restrict__ Wout, const float* __restrict__ bout,
                            float* __restrict__ out){
    int g = blockIdx.x, t = threadIdx.x;
    __shared__ float row[C];
    __shared__ float red[256];
    if (t < C) row[t] = d_gsum[g*PLN + t] / fmaxf(d_gcnt[g], 1.f);
    __syncthreads();
    for (int l = 0; l < 3; l++){
        float y = 0.f;
        if (t < C){
            #pragma unroll 4
            for (int k = 0; k < C; k++) y = fmaf(row[k], Wfc[(l*C + k)*C + t], y);
            y += bfc[l*C + t];
        }
        __syncthreads();
        if (t < C) row[t] = y;
        __syncthreads();
    }
    red[t] = (t < C) ? row[t]*Wout[t] : 0.f;
    __syncthreads();
    for (int s = 128; s > 0; s >>= 1){ if (t < s) red[t] += red[t + s]; __syncthreads(); }
    if (t == 0) out[g] = red[0] + bout[0];
}

extern "C" void kernel_launch(void* const* d_in, const int* in_sizes, int n_in,
                              void* d_out, int out_size){
    const int*   atoms = (const int*)d_in[0];
    const float* pos   = (const float*)d_in[1];
    const int*   ei    = (const int*)d_in[2];
    const int*   batch = (const int*)d_in[3];
    const float* emb   = (const float*)d_in[4];
    const float* Wf    = (const float*)d_in[5];
    const float* bf    = (const float*)d_in[6];
    const float* Ws    = (const float*)d_in[7];
    const float* bs    = (const float*)d_in[8];
    const float* Wfc   = (const float*)d_in[9];
    const float* bfc   = (const float*)d_in[10];
    const float* Wout  = (const float*)d_in[11];
    const float* bout  = (const float*)d_in[12];
    float* out = (float*)d_out;

    cudaFuncSetAttribute(node_gemm_kernel,
                         cudaFuncAttributeMaxDynamicSharedMemorySize, GSMEM);

    float *xa, *xb;
    cudaGetSymbolAddress((void**)&xa, d_xa);
    cudaGetSymbolAddress((void**)&xb, d_xb);

    pack_wbN_kernel<<<(NLAYERS*2*2*5*NPG*32 + 255)/256, 256>>>(Wf, Ws);
    pack_bph_kernel<<<(NLAYERS*2*NPG + 255)/256, 256>>>(bf, bs);
    pack_w3_kernel<<<(NLAYERS*NCOL + 255)/256, 256>>>(Wf, Ws);
    init_x_kernel<<<(NROWS*XS + 255)/256, 256>>>(atoms, pos, emb);

    zero_cnt_kernel<<<(N_NODES + 255)/256, 256>>>();
    hist_kernel<<<(N_EDGES + 255)/256, 256>>>(ei);
    scan_kernel<<<1, 1024>>>();
    scatter_kernel<<<(N_EDGES + 255)/256, 256>>>(ei, pos);
    dhist_kernel<<<(N_NODES + 255)/256, 256>>>();
    dscan_kernel<<<1, 32>>>();
    dorder_kernel<<<(N_NODES + 255)/256, 256>>>();

    float* cur = xa;
    float* nxt = xb;
    for (int l = 0; l < NLAYERS; l++){
        node_gemm_kernel<<<NROWS/128, 512, GSMEM>>>(cur, l);
        edge_csr_kernel<<<N_NODES/8, 256>>>(cur, nxt, l);
        edge_tail_kernel<<<N_EDGES/256, 256>>>(nxt, l);
        float* tmp = cur; cur = nxt; nxt = tmp;
    }

    zero_pool_kernel<<<(NUM_GRAPHS*PLN + 255)/256, 256>>>();
    pool_kernel<<<N_NODES/8, 256>>>(cur, batch);
    head_kernel<<<NUM_GRAPHS, 256>>>(Wfc, bfc, Wout, bout, out);
}

// round 14
// speedup vs baseline: 1.1278x; 1.0034x over previous
#include <cuda_runtime.h>
#include <cuda_bf16.h>
#include <cuda_fp16.h>
#include <cstdint>
#include <math.h>

#define N_NODES   50000
#define NROWS     50048
#define N_EDGES   800000
#define NUM_GRAPHS 256
#define C         129
#define ZDIM      259
#define NLAYERS   5
#define XS        160
#define PLN       132
#define NCOL      264
#define NPG       288
#define P2S       320
#define LN2       0.69314718f

// GEMM smem offsets
#define GSA    0
#define GSAL   43008
#define GSB    86016
#define GSSP   23040
#define GSBUF  46080
#define GSBI   178176
#define GSMEM  179328

__device__ __align__(16) __nv_bfloat16 d_wbN[NLAYERS*2*2*5*NPG*32];
__device__ float d_bph[NLAYERS*2*NPG];
__device__ float d_w3[NLAYERS*NCOL];
__device__ __align__(16) float d_xa[NROWS*XS];
__device__ __align__(16) float d_xb[NROWS*XS];
__device__ __align__(16) float  d_P1[(size_t)NROWS*NCOL];
__device__ __align__(16) __half d_P2h[(size_t)NROWS*P2S];
__device__ int   d_cnt[N_NODES];
__device__ int   d_rowptr[N_NODES + 1];
__device__ int   d_pos[N_NODES];
__device__ __align__(8) int2 d_edges[N_EDGES];
__device__ int   d_edst[N_EDGES];
__device__ int   d_dh[256];
__device__ int   d_dpos[256];
__device__ int   d_order[N_NODES];
__device__ float d_gsum[NUM_GRAPHS*PLN];
__device__ float d_gcnt[NUM_GRAPHS];

__device__ __host__ __forceinline__ void colmap(int n, int& pl, int& j){
    pl = (n >> 1) & 1;
    j  = 2*(n >> 2) + (n & 1);
}

__device__ __forceinline__ uint32_t smem_u32(const void* p){
    uint32_t a;
    asm("{ .reg .u64 t; cvta.to.shared.u64 t, %1; cvt.u32.u64 %0, t; }" : "=r"(a) : "l"(p));
    return a;
}
__device__ __forceinline__ void mma16816(float* d, uint32_t a0, uint32_t a1,
                                         uint32_t a2, uint32_t a3,
                                         uint32_t b0, uint32_t b1){
    asm volatile(
        "mma.sync.aligned.m16n8k16.row.col.f32.bf16.bf16.f32 "
        "{%0,%1,%2,%3}, {%4,%5,%6,%7}, {%8,%9}, {%0,%1,%2,%3};"
        : "+f"(d[0]), "+f"(d[1]), "+f"(d[2]), "+f"(d[3])
        : "r"(a0), "r"(a1), "r"(a2), "r"(a3), "r"(b0), "r"(b1));
}
__device__ __forceinline__ void cpasync16(uint32_t s, const void* g){
    asm volatile("cp.async.cg.shared.global [%0], [%1], 16;" :: "r"(s), "l"(g));
}
__device__ __forceinline__ void red4(float* p, float4 v){
    asm volatile("red.global.add.v4.f32 [%0], {%1,%2,%3,%4};"
                 :: "l"(p), "f"(v.x), "f"(v.y), "f"(v.z), "f"(v.w) : "memory");
}
__device__ __forceinline__ __half2 h2tanh_(__half2 x){
    uint32_t r, a = *(uint32_t*)&x;
    asm("tanh.approx.f16x2 %0, %1;" : "=r"(r) : "r"(a));
    return *(__half2*)&r;
}
__device__ __forceinline__ __half2 h2ex2_(__half2 x){
    uint32_t r, a = *(uint32_t*)&x;
    asm("ex2.approx.f16x2 %0, %1;" : "=r"(r) : "r"(a));
    return *(__half2*)&r;
}
__device__ __forceinline__ float sigf(float f){
    float t;
    asm("tanh.approx.f32 %0, %1;" : "=f"(t) : "f"(0.5f * f));
    return fmaf(0.5f, t, 0.5f);
}
__device__ __forceinline__ float gact(float f, float s){
    float sp = fmaxf(s, 0.f) + __logf(1.f + __expf(-fabsf(s)));
    return sigf(f) * sp;
}

// ---- prepack ----
__global__ void pack_wbN_kernel(const float* __restrict__ Wf, const float* __restrict__ Ws){
    int idx = blockIdx.x * blockDim.x + threadIdx.x;
    if (idx >= NLAYERS*2*2*5*NPG*32) return;
    int k  = idx & 31;
    int n  = (idx >> 5) % NPG;
    int kc = (idx / (32*NPG)) % 5;
    int sp = (idx / (32*NPG*5)) & 1;
    int hf = (idx / (32*NPG*5*2)) & 1;
    int l  = idx / (32*NPG*5*2*2);
    int kg = kc*32 + k;
    float w = 0.f;
    if (n < NCOL && kg < C){
        int pl, j; colmap(n, pl, j);
        if (j < C){
            int zi = hf ? (C + kg) : kg;
            const float* W = pl ? Ws : Wf;
            w = W[(l*ZDIM + zi)*C + j];
        }
    }
    __nv_bfloat16 hi = __float2bfloat16(w);
    d_wbN[idx] = sp ? __float2bfloat16(w - __bfloat162float(hi)) : hi;
}
__global__ void pack_bph_kernel(const float* __restrict__ bf, const float* __restrict__ bs){
    int idx = blockIdx.x * blockDim.x + threadIdx.x;
    if (idx >= NLAYERS*2*NPG) return;
    int n = idx % NPG, hf = (idx / NPG) & 1, l = idx / (2*NPG);
    float v = 0.f;
    if (hf == 0 && n < NCOL){
        int pl, j; colmap(n, pl, j);
        if (j < C) v = pl ? bs[l*C + j] : bf[l*C + j];
    }
    d_bph[idx] = v;
}
__global__ void pack_w3_kernel(const float* __restrict__ Wf, const float* __restrict__ Ws){
    int idx = blockIdx.x * blockDim.x + threadIdx.x;
    if (idx >= NLAYERS*NCOL) return;
    int n = idx % NCOL, l = idx / NCOL;
    int pl, j; colmap(n, pl, j);
    float v = 0.f;
    if (j < C){ const float* W = pl ? Ws : Wf; v = W[(l*ZDIM + 258)*C + j]; }
    d_w3[idx] = v;
}
__global__ void init_x_kernel(const int* __restrict__ atoms, const float* __restrict__ pos,
                              const float* __restrict__ emb){
    int idx = blockIdx.x * blockDim.x + threadIdx.x;
    if (idx >= NROWS*(XS/4)) return;
    int n = idx / (XS/4), c4 = idx - n*(XS/4);
    float4 v = make_float4(0.f, 0.f, 0.f, 0.f);
    if (n < N_NODES){
        if (c4 < 32) v = *(const float4*)(emb + (size_t)atoms[n]*128 + c4*4);
        else if (c4 == 32) v.x = pos[n*3 + 2];
    }
    *(float4*)(d_xa + (size_t)n*XS + c4*4) = v;
}

// ---- CSR build + degree-ordered schedule ----
__global__ void zero_cnt_kernel(){
    int i = blockIdx.x * blockDim.x + threadIdx.x;
    if (i < N_NODES) d_cnt[i] = 0;
    if (i < 256) d_dh[i] = 0;
}
__global__ void hist_kernel(const int* __restrict__ ei){
    int e = blockIdx.x * blockDim.x + threadIdx.x;
    if (e < N_EDGES) atomicAdd(&d_cnt[ei[N_EDGES + e]], 1);
}
__global__ void scan_kernel(){
    __shared__ int wsum[32];
    __shared__ int carry;
    int tid = threadIdx.x, lane = tid & 31, wid = tid >> 5;
    if (tid == 0) carry = 0;
    __syncthreads();
    for (int base = 0; base < N_NODES; base += 1024){
        int i = base + tid;
        int v = (i < N_NODES) ? d_cnt[i] : 0;
        int x = v;
        #pragma unroll
        for (int d = 1; d < 32; d <<= 1){
            int y = __shfl_up_sync(0xffffffffu, x, d);
            if (lane >= d) x += y;
        }
        if (lane == 31) wsum[wid] = x;
        __syncthreads();
        if (wid == 0){
            int s = wsum[lane];
            #pragma unroll
            for (int d = 1; d < 32; d <<= 1){
                int y = __shfl_up_sync(0xffffffffu, s, d);
                if (lane >= d) s += y;
            }
            wsum[lane] = s;
        }
        __syncthreads();
        int excl = x - v + (wid ? wsum[wid-1] : 0) + carry;
        if (i < N_NODES){ d_rowptr[i] = excl; d_pos[i] = excl; }
        __syncthreads();
        if (tid == 0) carry += wsum[31];
        __syncthreads();
    }
    if (threadIdx.x == 0) d_rowptr[N_NODES] = carry;
}
__global__ void scatter_kernel(const int* __restrict__ ei, const float* __restrict__ pos){
    int e = blockIdx.x * blockDim.x + threadIdx.x;
    if (e >= N_EDGES) return;
    int s = ei[e], d = ei[N_EDGES + e];
    float dx = pos[s*3]-pos[d*3], dy = pos[s*3+1]-pos[d*3+1], dz = pos[s*3+2]-pos[d*3+2];
    float eav = sqrtf(dx*dx + dy*dy + dz*dz);
    int p = atomicAdd(&d_pos[d], 1);
    d_edges[p] = make_int2(s, __float_as_int(eav));
    d_edst[p] = d;
}
__global__ void dhist_kernel(){
    int n = blockIdx.x * blockDim.x + threadIdx.x;
    if (n >= N_NODES) return;
    int d = min(d_cnt[n], 255);
    atomicAdd(&d_dh[d], 1);
}
__global__ void dscan_kernel(){
    if (threadIdx.x == 0){
        int acc = 0;
        for (int d = 255; d >= 0; d--){ d_dpos[d] = acc; acc += d_dh[d]; }
    }
}
__global__ void dorder_kernel(){
    int n = blockIdx.x * blockDim.x + threadIdx.x;
    if (n >= N_NODES) return;
    int d = min(d_cnt[n], 255);
    int p = atomicAdd(&d_dpos[d], 1);
    d_order[p] = n;
}

// ---- node GEMM: both halves in one CTA (A staged once) ----
__global__ __launch_bounds__(512, 1)
void node_gemm_kernel(const float* __restrict__ xc, int layer){
    extern __shared__ __align__(16) char smem[];
    uint32_t sb = smem_u32(smem);
    int tid = threadIdx.x, lane = tid & 31, wid = tid >> 5;
    int r0 = lane >> 2, tin = lane & 3;
    int warpM = wid & 3, warpN = wid >> 2;
    int m0 = blockIdx.x * 128;

    {
        int row = tid >> 2, q = tid & 3;
        const float4* xr = (const float4*)(xc + (size_t)(m0 + row)*XS) + q*10;
        char* arow = smem + GSA + row*336 + q*80;
        #pragma unroll
        for (int j = 0; j < 10; j++){
            float4 v = xr[j];
            __nv_bfloat16 hx = __float2bfloat16(v.x), hy = __float2bfloat16(v.y);
            __nv_bfloat16 hz = __float2bfloat16(v.z), hw = __float2bfloat16(v.w);
            __nv_bfloat162 h0(hx, hy), h1(hz, hw);
            __nv_bfloat162 l0(__float2bfloat16(v.x - __bfloat162float(hx)),
                              __float2bfloat16(v.y - __bfloat162float(hy)));
            __nv_bfloat162 l1(__float2bfloat16(v.z - __bfloat162float(hz)),
                              __float2bfloat16(v.w - __bfloat162float(hw)));
            *(uint2*)(arow + j*8)        = make_uint2(*(uint32_t*)&h0, *(uint32_t*)&h1);
            *(uint2*)(arow + GSAL + j*8) = make_uint2(*(uint32_t*)&l0, *(uint32_t*)&l1);
        }
    }

    uint32_t aoff = (uint32_t)((warpM*32 + r0)*336 + tin*4);
    uint32_t boff = (uint32_t)((warpN*72 + r0)*80 + tin*4);
    float* biS = (float*)(smem + GSBI);

    for (int hf = 0; hf < 2; hf++){
        const __nv_bfloat16* wbase = d_wbN + (size_t)((layer*2 + hf)*2) * 5*NPG*32;
        __syncthreads();
        #pragma unroll
        for (int pc = 0; pc < 2; pc++){
            for (int i = tid; i < 2304; i += 512){
                int sp = i / 1152, rr = i % 1152, n = rr >> 2, kv = rr & 3;
                const void* g = wbase + ((size_t)sp*5 + pc)*NPG*32 + n*32 + kv*8;
                cpasync16(sb + GSB + pc*GSBUF + sp*GSSP + n*80 + kv*16, g);
            }
            asm volatile("cp.async.commit_group;" ::: "memory");
        }
        for (int i = tid; i < NPG; i += 512) biS[i] = d_bph[(layer*2 + hf)*NPG + i];

        float acc[2][9][4];
        #pragma unroll
        for (int a = 0; a < 2; a++)
            #pragma unroll
            for (int b = 0; b < 9; b++)
                #pragma unroll
                for (int c = 0; c < 4; c++) acc[a][b][c] = 0.f;

        for (int sc = 0; sc < 5; sc++){
            int buf = sc & 1;
            if (sc == 4) asm volatile("cp.async.wait_group 0;" ::: "memory");
            else         asm volatile("cp.async.wait_group 1;" ::: "memory");
            __syncthreads();
            const char* bbuf = smem + GSB + buf*GSBUF;
            #pragma unroll
            for (int ks = 0; ks < 2; ks++){
                uint32_t ka = (uint32_t)(sc*32 + ks*16)*2;
                const char* ap = smem + GSA + aoff + ka;
                uint32_t ah[2][4], al[2][4];
                #pragma unroll
                for (int mt = 0; mt < 2; mt++){
                    const char* p = ap + mt*5376;
                    ah[mt][0] = *(const uint32_t*)(p);
                    ah[mt][1] = *(const uint32_t*)(p + 2688);
                    ah[mt][2] = *(const uint32_t*)(p + 16);
                    ah[mt][3] = *(const uint32_t*)(p + 2704);
                    const char* q = p + GSAL;
                    al[mt][0] = *(const uint32_t*)(q);
                    al[mt][1] = *(const uint32_t*)(q + 2688);
                    al[mt][2] = *(const uint32_t*)(q + 16);
                    al[mt][3] = *(const uint32_t*)(q + 2704);
                }
                uint32_t kb = (uint32_t)ks*32;
                #pragma unroll
                for (int nt = 0; nt < 9; nt++){
                    const char* bp = bbuf + boff + nt*640 + kb;
                    uint32_t bh0 = *(const uint32_t*)(bp);
                    uint32_t bh1 = *(const uint32_t*)(bp + 16);
                    uint32_t bl0 = *(const uint32_t*)(bp + GSSP);
                    uint32_t bl1 = *(const uint32_t*)(bp + GSSP + 16);
                    mma16816(acc[0][nt], ah[0][0], ah[0][1], ah[0][2], ah[0][3], bh0, bh1);
                    mma16816(acc[1][nt], ah[1][0], ah[1][1], ah[1][2], ah[1][3], bh0, bh1);
                    mma16816(acc[0][nt], al[0][0], al[0][1], al[0][2], al[0][3], bh0, bh1);
                    mma16816(acc[1][nt], al[1][0], al[1][1], al[1][2], al[1][3], bh0, bh1);
                    mma16816(acc[0][nt], ah[0][0], ah[0][1], ah[0][2], ah[0][3], bl0, bl1);
                    mma16816(acc[1][nt], ah[1][0], ah[1][1], ah[1][2], ah[1][3], bl0, bl1);
                }
            }
            __syncthreads();
            if (sc < 3){
                int nc = sc + 2;
                for (int i = tid; i < 2304; i += 512){
                    int sp = i / 1152, rr = i % 1152, n = rr >> 2, kv = rr & 3;
                    const void* g = wbase + ((size_t)sp*5 + nc)*NPG*32 + n*32 + kv*8;
                    cpasync16(sb + GSB + buf*GSBUF + sp*GSSP + n*80 + kv*16, g);
                }
                asm volatile("cp.async.commit_group;" ::: "memory");
            }
        }

        #pragma unroll
        for (int mt = 0; mt < 2; mt++){
            #pragma unroll
            for (int nt = 0; nt < 9; nt++){
                int col = warpN*72 + nt*8 + tin*2;
                if (col >= NCOL) continue;
                float b0 = biS[col], b1 = biS[col + 1];
                #pragma unroll
                for (int h = 0; h < 2; h++){
                    int row = m0 + warpM*32 + mt*16 + r0 + h*8;
                    float v0 = acc[mt][nt][2*h] + b0;
                    float v1 = acc[mt][nt][2*h+1] + b1;
                    if (hf == 0){
                        *(float2*)(d_P1 + (size_t)row*NCOL + col) = make_float2(v0, v1);
                    } else {
                        *(__half2*)(d_P2h + (size_t)row*P2S + col) = __floats2half2_rn(v0, v1);
                    }
                }
            }
        }
    }
}

// ---- edge phase: warp-per-node, f32 s-plane, half2-poly softplus log ----
__global__ __launch_bounds__(256)
void edge_csr_kernel(const float* __restrict__ xc, float* __restrict__ xn, int layer){
    int lane = threadIdx.x & 31, warp = threadIdx.x >> 5;
    int n = d_order[blockIdx.x * 8 + warp];
    int cb = lane * 8;
    const float* w3 = d_w3 + layer * NCOL;
    const float* p1 = d_P1 + (size_t)n * NCOL;
    float4 pa = *(const float4*)(p1 + cb);
    float4 pb = *(const float4*)(p1 + cb + 4);
    float4 wa = *(const float4*)(w3 + cb);
    float4 wb = *(const float4*)(w3 + cb + 4);
    // gate-plane half2 constants, pre-scaled by 0.5
    __half2 f1hA = __floats2half2_rn(0.5f*pa.x, 0.5f*pa.y);
    __half2 f1hB = __floats2half2_rn(0.5f*pb.x, 0.5f*pb.y);
    __half2 wfhA = __floats2half2_rn(0.5f*wa.x, 0.5f*wa.y);
    __half2 wfhB = __floats2half2_rn(0.5f*wb.x, 0.5f*wb.y);
    // s-plane f32 constants
    float s10=pa.z, s11=pa.w, s12=pb.z, s13=pb.w;
    float ws0=wa.z, ws1=wa.w, ws2=wb.z, ws3=wb.w;
    const __half2 h05 = __float2half2_rn(0.5f);
    const __half2 h1  = __float2half2_rn(1.0f);
    // lg2(1+u) poly coefficients, u in [0,1]
    const __half2 c0 = __float2half2_rn( 1.442695f);
    const __half2 c1 = __float2half2_rn(-0.713852f);
    const __half2 c2 = __float2half2_rn( 0.426624f);
    const __half2 c3 = __float2half2_rn(-0.204863f);
    const __half2 c4 = __float2half2_rn( 0.049396f);
    int beg = d_rowptr[n], end = d_rowptr[n + 1];
    float a0=0.f, a1=0.f, a2=0.f, a3=0.f;

    #pragma unroll 2
    for (int i = beg; i < end; i++){
        int2 e = d_edges[i];
        float ev = __int_as_float(e.y);
        const __half* q = d_P2h + (size_t)e.x * P2S;
        uint4 w = *(const uint4*)(q + cb);
        __half2 evh = __float2half2_rn(ev);
        // gate: t = tanh(0.5*(f1+f2+ev*wf))
        __half2 tA = h2tanh_(__hfma2(*(__half2*)&w.x, h05, __hfma2(evh, wfhA, f1hA)));
        __half2 tB = h2tanh_(__hfma2(*(__half2*)&w.z, h05, __hfma2(evh, wfhB, f1hB)));
        // s plane in f32 (bounded, NaN-free)
        float2 sy = __half22float2(*(__half2*)&w.y);
        float2 sw = __half22float2(*(__half2*)&w.w);
        float s0 = fmaf(ev, ws0, s10) + sy.x;
        float s1 = fmaf(ev, ws1, s11) + sy.y;
        float s2 = fmaf(ev, ws2, s12) + sw.x;
        float s3 = fmaf(ev, ws3, s13) + sw.y;
        // u = 2^(-|s|*log2e) in half2, then lg2(1+u) via degree-5 half2 poly
        __half2 uiA = __floats2half2_rn(fabsf(s0)*-1.44269504f, fabsf(s1)*-1.44269504f);
        __half2 uiB = __floats2half2_rn(fabsf(s2)*-1.44269504f, fabsf(s3)*-1.44269504f);
        __half2 uA = h2ex2_(uiA);
        __half2 uB = h2ex2_(uiB);
        __half2 pA = __hfma2(uA, c4, c3);
        pA = __hfma2(uA, pA, c2); pA = __hfma2(uA, pA, c1); pA = __hfma2(uA, pA, c0);
        pA = __hmul2(uA, pA);
        __half2 pB = __hfma2(uB, c4, c3);
        pB = __hfma2(uB, pB, c2); pB = __hfma2(uB, pB, c1); pB = __hfma2(uB, pB, c0);
        pB = __hmul2(uB, pB);
        float2 lg01 = __half22float2(pA);
        float2 lg23 = __half22float2(pB);
        float sp0 = fmaf(LN2, lg01.x, fmaxf(s0, 0.f));
        float sp1 = fmaf(LN2, lg01.y, fmaxf(s1, 0.f));
        float sp2 = fmaf(LN2, lg23.x, fmaxf(s2, 0.f));
        float sp3 = fmaf(LN2, lg23.y, fmaxf(s3, 0.f));
        // accumulate (1+t)*sp ; final 0.5 at writeback
        float2 tp01 = __half22float2(__hadd2(tA, h1));
        float2 tp23 = __half22float2(__hadd2(tB, h1));
        a0 = fmaf(tp01.x, sp0, a0);
        a1 = fmaf(tp01.y, sp1, a1);
        a2 = fmaf(tp23.x, sp2, a2);
        a3 = fmaf(tp23.y, sp3, a3);
    }

    float* xr = xn + (size_t)n * XS;
    const float* xcr = xc + (size_t)n * XS;
    float4 xv = *(const float4*)(xcr + lane*4);
    xv.x = fmaf(0.5f, a0, xv.x);
    xv.y = fmaf(0.5f, a1, xv.y);
    xv.z = fmaf(0.5f, a2, xv.z);
    xv.w = fmaf(0.5f, a3, xv.w);
    *(float4*)(xr + lane*4) = xv;
    if (lane == 0) xr[128] = xcr[128];
}

// ---- tail channel (128): one thread per edge, atomic accumulate ----
__global__ __launch_bounds__(256)
void edge_tail_kernel(float* __restrict__ xn, int layer){
    int e = blockIdx.x * 256 + threadIdx.x;
    int2 ed = d_edges[e];
    int dst = d_edst[e];
    float ev = __int_as_float(ed.y);
    const __half* q = d_P2h + (size_t)ed.x * P2S;
    uint2 tw = *(const uint2*)(q + 256);
    float4 pt = *(const float4*)(d_P1 + (size_t)dst*NCOL + 256);
    float wf = d_w3[layer*NCOL + 256];
    float ws = d_w3[layer*NCOL + 258];
    float2 tf = __half22float2(*(__half2*)&tw.x);
    float2 ts = __half22float2(*(__half2*)&tw.y);
    float m = gact(pt.x + tf.x + ev*wf, pt.z + ts.x + ev*ws);
    atomicAdd(xn + (size_t)dst*XS + 128, m);
}

// ---- pooling + head ----
__global__ void zero_pool_kernel(){
    int idx = blockIdx.x * blockDim.x + threadIdx.x;
    if (idx < NUM_GRAPHS*PLN) d_gsum[idx] = 0.f;
    if (idx < NUM_GRAPHS)     d_gcnt[idx] = 0.f;
}
__global__ __launch_bounds__(256)
void pool_kernel(const float* __restrict__ x, const int* __restrict__ batch){
    int lane = threadIdx.x & 31, warp = threadIdx.x >> 5;
    int n = blockIdx.x * 8 + warp;
    int b = batch[n];
    const float* xr = x + (size_t)n * XS;
    float4 v = *(const float4*)(xr + lane*4);
    red4(&d_gsum[b*PLN + lane*4], v);
    if (lane == 0) atomicAdd(&d_gsum[b*PLN + 128], xr[128]);
    if (lane == 1) atomicAdd(&d_gcnt[b], 1.f);
}
__global__ void head_kernel(const float* __restrict__ Wfc, const float* __restrict__ bfc,
                            const float* __restrict__ Wout, const float* __restrict__ bout,
                            float* __restrict__ out){
    int g = blockIdx.x, t = threadIdx.x;
    __shared__ float row[C];
    __shared__ float red[256];
    if (t < C) row[t] = d_gsum[g*PLN + t] / fmaxf(d_gcnt[g], 1.f);
    __syncthreads();
    for (int l = 0; l < 3; l++){
        float y = 0.f;
        if (t < C){
            #pragma unroll 4
            for (int k = 0; k < C; k++) y = fmaf(row[k], Wfc[(l*C + k)*C + t], y);
            y += bfc[l*C + t];
        }
        __syncthreads();
        if (t < C) row[t] = y;
        __syncthreads();
    }
    red[t] = (t < C) ? row[t]*Wout[t] : 0.f;
    __syncthreads();
    for (int s = 128; s > 0; s >>= 1){ if (t < s) red[t] += red[t + s]; __syncthreads(); }
    if (t == 0) out[g] = red[0] + bout[0];
}

extern "C" void kernel_launch(void* const* d_in, const int* in_sizes, int n_in,
                              void* d_out, int out_size){
    const int*   atoms = (const int*)d_in[0];
    const float* pos   = (const float*)d_in[1];
    const int*   ei    = (const int*)d_in[2];
    const int*   batch = (const int*)d_in[3];
    const float* emb   = (const float*)d_in[4];
    const float* Wf    = (const float*)d_in[5];
    const float* bf    = (const float*)d_in[6];
    const float* Ws    = (const float*)d_in[7];
    const float* bs    = (const float*)d_in[8];
    const float* Wfc   = (const float*)d_in[9];
    const float* bfc   = (const float*)d_in[10];
    const float* Wout  = (const float*)d_in[11];
    const float* bout  = (const float*)d_in[12];
    float* out = (float*)d_out;

    cudaFuncSetAttribute(node_gemm_kernel,
                         cudaFuncAttributeMaxDynamicSharedMemorySize, GSMEM);

    float *xa, *xb;
    cudaGetSymbolAddress((void**)&xa, d_xa);
    cudaGetSymbolAddress((void**)&xb, d_xb);

    pack_wbN_kernel<<<(NLAYERS*2*2*5*NPG*32 + 255)/256, 256>>>(Wf, Ws);
    pack_bph_kernel<<<(NLAYERS*2*NPG + 255)/256, 256>>>(bf, bs);
    pack_w3_kernel<<<(NLAYERS*NCOL + 255)/256, 256>>>(Wf, Ws);
    init_x_kernel<<<(NROWS*(XS/4) + 255)/256, 256>>>(atoms, pos, emb);

    zero_cnt_kernel<<<(N_NODES + 255)/256, 256>>>();
    hist_kernel<<<(N_EDGES + 255)/256, 256>>>(ei);
    scan_kernel<<<1, 1024>>>();
    scatter_kernel<<<(N_EDGES + 255)/256, 256>>>(ei, pos);
    dhist_kernel<<<(N_NODES + 255)/256, 256>>>();
    dscan_kernel<<<1, 32>>>();
    dorder_kernel<<<(N_NODES + 255)/256, 256>>>();

    float* cur = xa;
    float* nxt = xb;
    for (int l = 0; l < NLAYERS; l++){
        node_gemm_kernel<<<NROWS/128, 512, GSMEM>>>(cur, l);
        edge_csr_kernel<<<N_NODES/8, 256>>>(cur, nxt, l);
        edge_tail_kernel<<<N_EDGES/256, 256>>>(nxt, l);
        float* tmp = cur; cur = nxt; nxt = tmp;
    }

    zero_pool_kernel<<<(NUM_GRAPHS*PLN + 255)/256, 256>>>();
    pool_kernel<<<N_NODES/8, 256>>>(cur, batch);
    head_kernel<<<NUM_GRAPHS, 256>>>(Wfc, bfc, Wout, bout, out);
}

// round 16
// speedup vs baseline: 1.1599x; 1.0284x over previous
#include <cuda_runtime.h>
#include <cuda_bf16.h>
#include <cuda_fp16.h>
#include <cstdint>
#include <math.h>

#define N_NODES   50000
#define NROWS     50048
#define N_EDGES   800000
#define NUM_GRAPHS 256
#define C         129
#define ZDIM      259
#define NLAYERS   5
#define XS        160
#define PLN       132
#define NCOL      264
#define NPG       288
#define P2S       256      // P2h row = 512 B (hot channels only)
#define LN2       0.69314718f

// GEMM smem offsets
#define GSA    0
#define GSAL   43008
#define GSB    86016
#define GSSP   23040
#define GSBUF  46080
#define GSBI   178176
#define GSMEM  179328

__device__ __align__(16) __nv_bfloat16 d_wbN[NLAYERS*2*2*5*NPG*32];
__device__ float d_bph[NLAYERS*2*NPG];
__device__ float d_w3[NLAYERS*NCOL];
__device__ __align__(16) float d_xa[NROWS*XS];
__device__ __align__(16) float d_xb[NROWS*XS];
__device__ __align__(16) float  d_P1[(size_t)NROWS*NCOL];
__device__ __align__(16) __half d_P2h[(size_t)NROWS*P2S];
__device__ __align__(4)  __half d_P2t[NROWS*2];
__device__ int   d_cnt[N_NODES];
__device__ int   d_rowptr[N_NODES + 1];
__device__ int   d_pos[N_NODES];
__device__ __align__(8) int2 d_edges[N_EDGES];
__device__ int   d_edst[N_EDGES];
__device__ int   d_dh[256];
__device__ int   d_dpos[256];
__device__ int   d_order[N_NODES];
__device__ float d_gsum[NUM_GRAPHS*PLN];
__device__ float d_gcnt[NUM_GRAPHS];

__device__ __host__ __forceinline__ void colmap(int n, int& pl, int& j){
    pl = (n >> 1) & 1;
    j  = 2*(n >> 2) + (n & 1);
}

__device__ __forceinline__ uint32_t smem_u32(const void* p){
    uint32_t a;
    asm("{ .reg .u64 t; cvta.to.shared.u64 t, %1; cvt.u32.u64 %0, t; }" : "=r"(a) : "l"(p));
    return a;
}
__device__ __forceinline__ void mma16816(float* d, uint32_t a0, uint32_t a1,
                                         uint32_t a2, uint32_t a3,
                                         uint32_t b0, uint32_t b1){
    asm volatile(
        "mma.sync.aligned.m16n8k16.row.col.f32.bf16.bf16.f32 "
        "{%0,%1,%2,%3}, {%4,%5,%6,%7}, {%8,%9}, {%0,%1,%2,%3};"
        : "+f"(d[0]), "+f"(d[1]), "+f"(d[2]), "+f"(d[3])
        : "r"(a0), "r"(a1), "r"(a2), "r"(a3), "r"(b0), "r"(b1));
}
__device__ __forceinline__ void cpasync16(uint32_t s, const void* g){
    asm volatile("cp.async.cg.shared.global [%0], [%1], 16;" :: "r"(s), "l"(g));
}
__device__ __forceinline__ void red4(float* p, float4 v){
    asm volatile("red.global.add.v4.f32 [%0], {%1,%2,%3,%4};"
                 :: "l"(p), "f"(v.x), "f"(v.y), "f"(v.z), "f"(v.w) : "memory");
}
__device__ __forceinline__ uint64_t mkpol_last(){
    uint64_t p;
    asm("createpolicy.fractional.L2::evict_last.b64 %0, 1.0;" : "=l"(p));
    return p;
}
__device__ __forceinline__ uint64_t mkpol_first(){
    uint64_t p;
    asm("createpolicy.fractional.L2::evict_first.b64 %0, 1.0;" : "=l"(p));
    return p;
}
// gather load, pinned toward L2 residency via cache-hint policy
__device__ __forceinline__ uint4 ldg_pol4(const void* p, uint64_t pol){
    uint4 v;
    asm volatile("ld.global.nc.L2::cache_hint.v4.u32 {%0,%1,%2,%3}, [%4], %5;"
                 : "=r"(v.x), "=r"(v.y), "=r"(v.z), "=r"(v.w) : "l"(p), "l"(pol));
    return v;
}
__device__ __forceinline__ float4 ldg_polf4(const float* p, uint64_t pol){
    float4 v;
    asm volatile("ld.global.nc.L2::cache_hint.v4.f32 {%0,%1,%2,%3}, [%4], %5;"
                 : "=f"(v.x), "=f"(v.y), "=f"(v.z), "=f"(v.w) : "l"(p), "l"(pol));
    return v;
}
__device__ __forceinline__ __half2 h2tanh_(__half2 x){
    uint32_t r, a = *(uint32_t*)&x;
    asm("tanh.approx.f16x2 %0, %1;" : "=r"(r) : "r"(a));
    return *(__half2*)&r;
}
__device__ __forceinline__ __half2 h2ex2_(__half2 x){
    uint32_t r, a = *(uint32_t*)&x;
    asm("ex2.approx.f16x2 %0, %1;" : "=r"(r) : "r"(a));
    return *(__half2*)&r;
}
__device__ __forceinline__ float sigf(float f){
    float t;
    asm("tanh.approx.f32 %0, %1;" : "=f"(t) : "f"(0.5f * f));
    return fmaf(0.5f, t, 0.5f);
}
__device__ __forceinline__ float gact(float f, float s){
    float sp = fmaxf(s, 0.f) + __logf(1.f + __expf(-fabsf(s)));
    return sigf(f) * sp;
}

// ---- prepack ----
__global__ void pack_wbN_kernel(const float* __restrict__ Wf, const float* __restrict__ Ws){
    int idx = blockIdx.x * blockDim.x + threadIdx.x;
    if (idx >= NLAYERS*2*2*5*NPG*32) return;
    int k  = idx & 31;
    int n  = (idx >> 5) % NPG;
    int kc = (idx / (32*NPG)) % 5;
    int sp = (idx / (32*NPG*5)) & 1;
    int hf = (idx / (32*NPG*5*2)) & 1;
    int l  = idx / (32*NPG*5*2*2);
    int kg = kc*32 + k;
    float w = 0.f;
    if (n < NCOL && kg < C){
        int pl, j; colmap(n, pl, j);
        if (j < C){
            int zi = hf ? (C + kg) : kg;
            const float* W = pl ? Ws : Wf;
            w = W[(l*ZDIM + zi)*C + j];
        }
    }
    __nv_bfloat16 hi = __float2bfloat16(w);
    d_wbN[idx] = sp ? __float2bfloat16(w - __bfloat162float(hi)) : hi;
}
__global__ void pack_bph_kernel(const float* __restrict__ bf, const float* __restrict__ bs){
    int idx = blockIdx.x * blockDim.x + threadIdx.x;
    if (idx >= NLAYERS*2*NPG) return;
    int n = idx % NPG, hf = (idx / NPG) & 1, l = idx / (2*NPG);
    float v = 0.f;
    if (hf == 0 && n < NCOL){
        int pl, j; colmap(n, pl, j);
        if (j < C) v = pl ? bs[l*C + j] : bf[l*C + j];
    }
    d_bph[idx] = v;
}
__global__ void pack_w3_kernel(const float* __restrict__ Wf, const float* __restrict__ Ws){
    int idx = blockIdx.x * blockDim.x + threadIdx.x;
    if (idx >= NLAYERS*NCOL) return;
    int n = idx % NCOL, l = idx / NCOL;
    int pl, j; colmap(n, pl, j);
    float v = 0.f;
    if (j < C){ const float* W = pl ? Ws : Wf; v = W[(l*ZDIM + 258)*C + j]; }
    d_w3[idx] = v;
}
__global__ void init_x_kernel(const int* __restrict__ atoms, const float* __restrict__ pos,
                              const float* __restrict__ emb){
    int idx = blockIdx.x * blockDim.x + threadIdx.x;
    if (idx >= NROWS*(XS/4)) return;
    int n = idx / (XS/4), c4 = idx - n*(XS/4);
    float4 v = make_float4(0.f, 0.f, 0.f, 0.f);
    if (n < N_NODES){
        if (c4 < 32) v = *(const float4*)(emb + (size_t)atoms[n]*128 + c4*4);
        else if (c4 == 32) v.x = pos[n*3 + 2];
    }
    *(float4*)(d_xa + (size_t)n*XS + c4*4) = v;
}

// ---- CSR build + degree-ordered schedule ----
__global__ void zero_cnt_kernel(){
    int i = blockIdx.x * blockDim.x + threadIdx.x;
    if (i < N_NODES) d_cnt[i] = 0;
    if (i < 256) d_dh[i] = 0;
}
__global__ void hist_kernel(const int* __restrict__ ei){
    int e = blockIdx.x * blockDim.x + threadIdx.x;
    if (e < N_EDGES) atomicAdd(&d_cnt[ei[N_EDGES + e]], 1);
}
__global__ void scan_kernel(){
    __shared__ int wsum[32];
    __shared__ int carry;
    int tid = threadIdx.x, lane = tid & 31, wid = tid >> 5;
    if (tid == 0) carry = 0;
    __syncthreads();
    for (int base = 0; base < N_NODES; base += 1024){
        int i = base + tid;
        int v = (i < N_NODES) ? d_cnt[i] : 0;
        int x = v;
        #pragma unroll
        for (int d = 1; d < 32; d <<= 1){
            int y = __shfl_up_sync(0xffffffffu, x, d);
            if (lane >= d) x += y;
        }
        if (lane == 31) wsum[wid] = x;
        __syncthreads();
        if (wid == 0){
            int s = wsum[lane];
            #pragma unroll
            for (int d = 1; d < 32; d <<= 1){
                int y = __shfl_up_sync(0xffffffffu, s, d);
                if (lane >= d) s += y;
            }
            wsum[lane] = s;
        }
        __syncthreads();
        int excl = x - v + (wid ? wsum[wid-1] : 0) + carry;
        if (i < N_NODES){ d_rowptr[i] = excl; d_pos[i] = excl; }
        __syncthreads();
        if (tid == 0) carry += wsum[31];
        __syncthreads();
    }
    if (threadIdx.x == 0) d_rowptr[N_NODES] = carry;
}
__global__ void scatter_kernel(const int* __restrict__ ei, const float* __restrict__ pos){
    int e = blockIdx.x * blockDim.x + threadIdx.x;
    if (e >= N_EDGES) return;
    int s = ei[e], d = ei[N_EDGES + e];
    float dx = pos[s*3]-pos[d*3], dy = pos[s*3+1]-pos[d*3+1], dz = pos[s*3+2]-pos[d*3+2];
    float eav = sqrtf(dx*dx + dy*dy + dz*dz);
    int p = atomicAdd(&d_pos[d], 1);
    d_edges[p] = make_int2(s, __float_as_int(eav));
    d_edst[p] = d;
}
__global__ void dhist_kernel(){
    int n = blockIdx.x * blockDim.x + threadIdx.x;
    if (n >= N_NODES) return;
    int d = min(d_cnt[n], 255);
    atomicAdd(&d_dh[d], 1);
}
__global__ void dscan_kernel(){
    if (threadIdx.x == 0){
        int acc = 0;
        for (int d = 255; d >= 0; d--){ d_dpos[d] = acc; acc += d_dh[d]; }
    }
}
__global__ void dorder_kernel(){
    int n = blockIdx.x * blockDim.x + threadIdx.x;
    if (n >= N_NODES) return;
    int d = min(d_cnt[n], 255);
    int p = atomicAdd(&d_dpos[d], 1);
    d_order[p] = n;
}

// ---- node GEMM: both halves in one CTA (A staged once) ----
__global__ __launch_bounds__(512, 1)
void node_gemm_kernel(const float* __restrict__ xc, int layer){
    extern __shared__ __align__(16) char smem[];
    uint32_t sb = smem_u32(smem);
    int tid = threadIdx.x, lane = tid & 31, wid = tid >> 5;
    int r0 = lane >> 2, tin = lane & 3;
    int warpM = wid & 3, warpN = wid >> 2;
    int m0 = blockIdx.x * 128;

    {
        int row = tid >> 2, q = tid & 3;
        const float4* xr = (const float4*)(xc + (size_t)(m0 + row)*XS) + q*10;
        char* arow = smem + GSA + row*336 + q*80;
        #pragma unroll
        for (int j = 0; j < 10; j++){
            float4 v = xr[j];
            __nv_bfloat16 hx = __float2bfloat16(v.x), hy = __float2bfloat16(v.y);
            __nv_bfloat16 hz = __float2bfloat16(v.z), hw = __float2bfloat16(v.w);
            __nv_bfloat162 h0(hx, hy), h1(hz, hw);
            __nv_bfloat162 l0(__float2bfloat16(v.x - __bfloat162float(hx)),
                              __float2bfloat16(v.y - __bfloat162float(hy)));
            __nv_bfloat162 l1(__float2bfloat16(v.z - __bfloat162float(hz)),
                              __float2bfloat16(v.w - __bfloat162float(hw)));
            *(uint2*)(arow + j*8)        = make_uint2(*(uint32_t*)&h0, *(uint32_t*)&h1);
            *(uint2*)(arow + GSAL + j*8) = make_uint2(*(uint32_t*)&l0, *(uint32_t*)&l1);
        }
    }

    uint32_t aoff = (uint32_t)((warpM*32 + r0)*336 + tin*4);
    uint32_t boff = (uint32_t)((warpN*72 + r0)*80 + tin*4);
    float* biS = (float*)(smem + GSBI);

    for (int hf = 0; hf < 2; hf++){
        const __nv_bfloat16* wbase = d_wbN + (size_t)((layer*2 + hf)*2) * 5*NPG*32;
        __syncthreads();
        #pragma unroll
        for (int pc = 0; pc < 2; pc++){
            for (int i = tid; i < 2304; i += 512){
                int sp = i / 1152, rr = i % 1152, n = rr >> 2, kv = rr & 3;
                const void* g = wbase + ((size_t)sp*5 + pc)*NPG*32 + n*32 + kv*8;
                cpasync16(sb + GSB + pc*GSBUF + sp*GSSP + n*80 + kv*16, g);
            }
            asm volatile("cp.async.commit_group;" ::: "memory");
        }
        for (int i = tid; i < NPG; i += 512) biS[i] = d_bph[(layer*2 + hf)*NPG + i];

        float acc[2][9][4];
        #pragma unroll
        for (int a = 0; a < 2; a++)
            #pragma unroll
            for (int b = 0; b < 9; b++)
                #pragma unroll
                for (int c = 0; c < 4; c++) acc[a][b][c] = 0.f;

        for (int sc = 0; sc < 5; sc++){
            int buf = sc & 1;
            if (sc == 4) asm volatile("cp.async.wait_group 0;" ::: "memory");
            else         asm volatile("cp.async.wait_group 1;" ::: "memory");
            __syncthreads();
            const char* bbuf = smem + GSB + buf*GSBUF;
            #pragma unroll
            for (int ks = 0; ks < 2; ks++){
                uint32_t ka = (uint32_t)(sc*32 + ks*16)*2;
                const char* ap = smem + GSA + aoff + ka;
                uint32_t ah[2][4], al[2][4];
                #pragma unroll
                for (int mt = 0; mt < 2; mt++){
                    const char* p = ap + mt*5376;
                    ah[mt][0] = *(const uint32_t*)(p);
                    ah[mt][1] = *(const uint32_t*)(p + 2688);
                    ah[mt][2] = *(const uint32_t*)(p + 16);
                    ah[mt][3] = *(const uint32_t*)(p + 2704);
                    const char* q = p + GSAL;
                    al[mt][0] = *(const uint32_t*)(q);
                    al[mt][1] = *(const uint32_t*)(q + 2688);
                    al[mt][2] = *(const uint32_t*)(q + 16);
                    al[mt][3] = *(const uint32_t*)(q + 2704);
                }
                uint32_t kb = (uint32_t)ks*32;
                #pragma unroll
                for (int nt = 0; nt < 9; nt++){
                    const char* bp = bbuf + boff + nt*640 + kb;
                    uint32_t bh0 = *(const uint32_t*)(bp);
                    uint32_t bh1 = *(const uint32_t*)(bp + 16);
                    uint32_t bl0 = *(const uint32_t*)(bp + GSSP);
                    uint32_t bl1 = *(const uint32_t*)(bp + GSSP + 16);
                    mma16816(acc[0][nt], ah[0][0], ah[0][1], ah[0][2], ah[0][3], bh0, bh1);
                    mma16816(acc[1][nt], ah[1][0], ah[1][1], ah[1][2], ah[1][3], bh0, bh1);
                    mma16816(acc[0][nt], al[0][0], al[0][1], al[0][2], al[0][3], bh0, bh1);
                    mma16816(acc[1][nt], al[1][0], al[1][1], al[1][2], al[1][3], bh0, bh1);
                    mma16816(acc[0][nt], ah[0][0], ah[0][1], ah[0][2], ah[0][3], bl0, bl1);
                    mma16816(acc[1][nt], ah[1][0], ah[1][1], ah[1][2], ah[1][3], bl0, bl1);
                }
            }
            __syncthreads();
            if (sc < 3){
                int nc = sc + 2;
                for (int i = tid; i < 2304; i += 512){
                    int sp = i / 1152, rr = i % 1152, n = rr >> 2, kv = rr & 3;
                    const void* g = wbase + ((size_t)sp*5 + nc)*NPG*32 + n*32 + kv*8;
                    cpasync16(sb + GSB + buf*GSBUF + sp*GSSP + n*80 + kv*16, g);
                }
                asm volatile("cp.async.commit_group;" ::: "memory");
            }
        }

        #pragma unroll
        for (int mt = 0; mt < 2; mt++){
            #pragma unroll
            for (int nt = 0; nt < 9; nt++){
                int col = warpN*72 + nt*8 + tin*2;
                if (col >= NCOL) continue;
                float b0 = biS[col], b1 = biS[col + 1];
                #pragma unroll
                for (int h = 0; h < 2; h++){
                    int row = m0 + warpM*32 + mt*16 + r0 + h*8;
                    float v0 = acc[mt][nt][2*h] + b0;
                    float v1 = acc[mt][nt][2*h+1] + b1;
                    if (hf == 0){
                        *(float2*)(d_P1 + (size_t)row*NCOL + col) = make_float2(v0, v1);
                    } else {
                        if (col < 256)
                            *(__half2*)(d_P2h + (size_t)row*P2S + col) = __floats2half2_rn(v0, v1);
                        else if (col == 256)
                            d_P2t[row*2]     = __float2half(v0);
                        else if (col == 258)
                            d_P2t[row*2 + 1] = __float2half(v0);
                    }
                }
            }
        }
    }
}

// ---- edge phase: warp-per-node, policy-pinned gather, half2-poly softplus ----
__global__ __launch_bounds__(256)
void edge_csr_kernel(const float* __restrict__ xc, float* __restrict__ xn, int layer){
    int lane = threadIdx.x & 31, warp = threadIdx.x >> 5;
    int n = d_order[blockIdx.x * 8 + warp];
    int cb = lane * 8;
    uint64_t pol_l = mkpol_last();
    uint64_t pol_f = mkpol_first();
    const float* w3 = d_w3 + layer * NCOL;
    const float* p1 = d_P1 + (size_t)n * NCOL;
    float4 pa = ldg_polf4(p1 + cb, pol_f);
    float4 pb = ldg_polf4(p1 + cb + 4, pol_f);
    float4 wa = *(const float4*)(w3 + cb);
    float4 wb = *(const float4*)(w3 + cb + 4);
    __half2 f1hA = __floats2half2_rn(0.5f*pa.x, 0.5f*pa.y);
    __half2 f1hB = __floats2half2_rn(0.5f*pb.x, 0.5f*pb.y);
    __half2 wfhA = __floats2half2_rn(0.5f*wa.x, 0.5f*wa.y);
    __half2 wfhB = __floats2half2_rn(0.5f*wb.x, 0.5f*wb.y);
    float s10=pa.z, s11=pa.w, s12=pb.z, s13=pb.w;
    float ws0=wa.z, ws1=wa.w, ws2=wb.z, ws3=wb.w;
    const __half2 h05 = __float2half2_rn(0.5f);
    const __half2 h1  = __float2half2_rn(1.0f);
    const __half2 c0 = __float2half2_rn( 1.442695f);
    const __half2 c1 = __float2half2_rn(-0.713852f);
    const __half2 c2 = __float2half2_rn( 0.426624f);
    const __half2 c3 = __float2half2_rn(-0.204863f);
    const __half2 c4 = __float2half2_rn( 0.049396f);
    int beg = d_rowptr[n], end = d_rowptr[n + 1];
    float a0=0.f, a1=0.f, a2=0.f, a3=0.f;

    #pragma unroll 2
    for (int i = beg; i < end; i++){
        int2 e = d_edges[i];
        float ev = __int_as_float(e.y);
        const __half* q = d_P2h + (size_t)e.x * P2S;
        uint4 w = ldg_pol4(q + cb, pol_l);
        __half2 evh = __float2half2_rn(ev);
        __half2 tA = h2tanh_(__hfma2(*(__half2*)&w.x, h05, __hfma2(evh, wfhA, f1hA)));
        __half2 tB = h2tanh_(__hfma2(*(__half2*)&w.z, h05, __hfma2(evh, wfhB, f1hB)));
        float2 sy = __half22float2(*(__half2*)&w.y);
        float2 sw = __half22float2(*(__half2*)&w.w);
        float s0 = fmaf(ev, ws0, s10) + sy.x;
        float s1 = fmaf(ev, ws1, s11) + sy.y;
        float s2 = fmaf(ev, ws2, s12) + sw.x;
        float s3 = fmaf(ev, ws3, s13) + sw.y;
        __half2 uiA = __floats2half2_rn(fabsf(s0)*-1.44269504f, fabsf(s1)*-1.44269504f);
        __half2 uiB = __floats2half2_rn(fabsf(s2)*-1.44269504f, fabsf(s3)*-1.44269504f);
        __half2 uA = h2ex2_(uiA);
        __half2 uB = h2ex2_(uiB);
        __half2 pA = __hfma2(uA, c4, c3);
        pA = __hfma2(uA, pA, c2); pA = __hfma2(uA, pA, c1); pA = __hfma2(uA, pA, c0);
        pA = __hmul2(uA, pA);
        __half2 pB = __hfma2(uB, c4, c3);
        pB = __hfma2(uB, pB, c2); pB = __hfma2(uB, pB, c1); pB = __hfma2(uB, pB, c0);
        pB = __hmul2(uB, pB);
        float2 lg01 = __half22float2(pA);
        float2 lg23 = __half22float2(pB);
        float sp0 = fmaf(LN2, lg01.x, fmaxf(s0, 0.f));
        float sp1 = fmaf(LN2, lg01.y, fmaxf(s1, 0.f));
        float sp2 = fmaf(LN2, lg23.x, fmaxf(s2, 0.f));
        float sp3 = fmaf(LN2, lg23.y, fmaxf(s3, 0.f));
        float2 tp01 = __half22float2(__hadd2(tA, h1));
        float2 tp23 = __half22float2(__hadd2(tB, h1));
        a0 = fmaf(tp01.x, sp0, a0);
        a1 = fmaf(tp01.y, sp1, a1);
        a2 = fmaf(tp23.x, sp2, a2);
        a3 = fmaf(tp23.y, sp3, a3);
    }

    float* xr = xn + (size_t)n * XS;
    const float* xcr = xc + (size_t)n * XS;
    float4 xv = ldg_polf4(xcr + lane*4, pol_f);
    xv.x = fmaf(0.5f, a0, xv.x);
    xv.y = fmaf(0.5f, a1, xv.y);
    xv.z = fmaf(0.5f, a2, xv.z);
    xv.w = fmaf(0.5f, a3, xv.w);
    *(float4*)(xr + lane*4) = xv;
    if (lane == 0) xr[128] = xcr[128];
}

// ---- tail channel (128): one thread per edge, atomic accumulate ----
__global__ __launch_bounds__(256)
void edge_tail_kernel(float* __restrict__ xn, int layer){
    int e = blockIdx.x * 256 + threadIdx.x;
    int2 ed = d_edges[e];
    int dst = d_edst[e];
    float ev = __int_as_float(ed.y);
    __half2 t2 = *(const __half2*)(d_P2t + ed.x*2);
    float4 pt = *(const float4*)(d_P1 + (size_t)dst*NCOL + 256);
    float wf = d_w3[layer*NCOL + 256];
    float ws = d_w3[layer*NCOL + 258];
    float2 tv = __half22float2(t2);
    float m = gact(pt.x + tv.x + ev*wf, pt.z + tv.y + ev*ws);
    atomicAdd(xn + (size_t)dst*XS + 128, m);
}

// ---- pooling + head ----
__global__ void zero_pool_kernel(){
    int idx = blockIdx.x * blockDim.x + threadIdx.x;
    if (idx < NUM_GRAPHS*PLN) d_gsum[idx] = 0.f;
    if (idx < NUM_GRAPHS)     d_gcnt[idx] = 0.f;
}
__global__ __launch_bounds__(256)
void pool_kernel(const float* __restrict__ x, const int* __restrict__ batch){
    int lane = threadIdx.x & 31, warp = threadIdx.x >> 5;
    int n = blockIdx.x * 8 + warp;
    int b = batch[n];
    const float* xr = x + (size_t)n * XS;
    float4 v = *(const float4*)(xr + lane*4);
    red4(&d_gsum[b*PLN + lane*4], v);
    if (lane == 0) atomicAdd(&d_gsum[b*PLN + 128], xr[128]);
    if (lane == 1) atomicAdd(&d_gcnt[b], 1.f);
}
__global__ void head_kernel(const float* __restrict__ Wfc, const float* __restrict__ bfc,
                            const float* __restrict__ Wout, const float* __restrict__ bout,
                            float* __restrict__ out){
    int g = blockIdx.x, t = threadIdx.x;
    __shared__ float row[C];
    __shared__ float red[256];
    if (t < C) row[t] = d_gsum[g*PLN + t] / fmaxf(d_gcnt[g], 1.f);
    __syncthreads();
    for (int l = 0; l < 3; l++){
        float y = 0.f;
        if (t < C){
            #pragma unroll 4
            for (int k = 0; k < C; k++) y = fmaf(row[k], Wfc[(l*C + k)*C + t], y);
            y += bfc[l*C + t];
        }
        __syncthreads();
        if (t < C) row[t] = y;
        __syncthreads();
    }
    red[t] = (t < C) ? row[t]*Wout[t] : 0.f;
    __syncthreads();
    for (int s = 128; s > 0; s >>= 1){ if (t < s) red[t] += red[t + s]; __syncthreads(); }
    if (t == 0) out[g] = red[0] + bout[0];
}

extern "C" void kernel_launch(void* const* d_in, const int* in_sizes, int n_in,
                              void* d_out, int out_size){
    const int*   atoms = (const int*)d_in[0];
    const float* pos   = (const float*)d_in[1];
    const int*   ei    = (const int*)d_in[2];
    const int*   batch = (const int*)d_in[3];
    const float* emb   = (const float*)d_in[4];
    const float* Wf    = (const float*)d_in[5];
    const float* bf    = (const float*)d_in[6];
    const float* Ws    = (const float*)d_in[7];
    const float* bs    = (const float*)d_in[8];
    const float* Wfc   = (const float*)d_in[9];
    const float* bfc   = (const float*)d_in[10];
    const float* Wout  = (const float*)d_in[11];
    const float* bout  = (const float*)d_in[12];
    float* out = (float*)d_out;

    cudaFuncSetAttribute(node_gemm_kernel,
                         cudaFuncAttributeMaxDynamicSharedMemorySize, GSMEM);

    float *xa, *xb;
    cudaGetSymbolAddress((void**)&xa, d_xa);
    cudaGetSymbolAddress((void**)&xb, d_xb);

    pack_wbN_kernel<<<(NLAYERS*2*2*5*NPG*32 + 255)/256, 256>>>(Wf, Ws);
    pack_bph_kernel<<<(NLAYERS*2*NPG + 255)/256, 256>>>(bf, bs);
    pack_w3_kernel<<<(NLAYERS*NCOL + 255)/256, 256>>>(Wf, Ws);
    init_x_kernel<<<(NROWS*(XS/4) + 255)/256, 256>>>(atoms, pos, emb);

    zero_cnt_kernel<<<(N_NODES + 255)/256, 256>>>();
    hist_kernel<<<(N_EDGES + 255)/256, 256>>>(ei);
    scan_kernel<<<1, 1024>>>();
    scatter_kernel<<<(N_EDGES + 255)/256, 256>>>(ei, pos);
    dhist_kernel<<<(N_NODES + 255)/256, 256>>>();
    dscan_kernel<<<1, 32>>>();
    dorder_kernel<<<(N_NODES + 255)/256, 256>>>();

    float* cur = xa;
    float* nxt = xb;
    for (int l = 0; l < NLAYERS; l++){
        node_gemm_kernel<<<NROWS/128, 512, GSMEM>>>(cur, l);
        edge_csr_kernel<<<N_NODES/8, 256>>>(cur, nxt, l);
        edge_tail_kernel<<<N_EDGES/256, 256>>>(nxt, l);
        float* tmp = cur; cur = nxt; nxt = tmp;
    }

    zero_pool_kernel<<<(NUM_GRAPHS*PLN + 255)/256, 256>>>();
    pool_kernel<<<N_NODES/8, 256>>>(cur, batch);
    head_kernel<<<NUM_GRAPHS, 256>>>(Wfc, bfc, Wout, bout, out);
}

// round 17
// speedup vs baseline: 1.2694x; 1.0943x over previous
#include <cuda_runtime.h>
#include <cuda_bf16.h>
#include <cuda_fp16.h>
#include <cstdint>
#include <math.h>

#define N_NODES   50000
#define NROWS     50048
#define N_EDGES   800000
#define NUM_GRAPHS 256
#define C         129
#define ZDIM      259
#define NLAYERS   5
#define XS        160
#define PLN       132
#define NCOL      264
#define NPG       288
#define P2S       256
#define LN2       0.69314718f

// GEMM smem offsets (A-lo staging removed)
#define GSA    0            // A hi: 128 x 336B = 43008
#define GSB    43008        // B: 2 bufs x (2 splits x 288 x 80B)
#define GSSP   23040
#define GSBUF  46080
#define GSBI   135168       // bias 288 f32
#define GSMEM  136320

__device__ __align__(16) __nv_bfloat16 d_wbN[NLAYERS*2*2*5*NPG*32];
__device__ float d_bph[NLAYERS*2*NPG];
__device__ float d_w3[NLAYERS*NCOL];
__device__ __align__(16) float d_xa[NROWS*XS];
__device__ __align__(16) float d_xb[NROWS*XS];
__device__ __align__(16) float  d_P1[(size_t)NROWS*NCOL];
__device__ __align__(16) __half d_P2h[(size_t)NROWS*P2S];
__device__ __align__(4)  __half d_P2t[NROWS*2];
__device__ int   d_cnt[N_NODES];
__device__ int   d_rowptr[N_NODES + 1];
__device__ int   d_pos[N_NODES];
__device__ __align__(8) int2 d_edges[N_EDGES];
__device__ int   d_edst[N_EDGES];
__device__ int   d_dh[256];
__device__ int   d_dpos[256];
__device__ int   d_order[N_NODES];
__device__ float d_gsum[NUM_GRAPHS*PLN];
__device__ float d_gcnt[NUM_GRAPHS];

__device__ __host__ __forceinline__ void colmap(int n, int& pl, int& j){
    pl = (n >> 1) & 1;
    j  = 2*(n >> 2) + (n & 1);
}

__device__ __forceinline__ uint32_t smem_u32(const void* p){
    uint32_t a;
    asm("{ .reg .u64 t; cvta.to.shared.u64 t, %1; cvt.u32.u64 %0, t; }" : "=r"(a) : "l"(p));
    return a;
}
__device__ __forceinline__ void mma16816(float* d, uint32_t a0, uint32_t a1,
                                         uint32_t a2, uint32_t a3,
                                         uint32_t b0, uint32_t b1){
    asm volatile(
        "mma.sync.aligned.m16n8k16.row.col.f32.bf16.bf16.f32 "
        "{%0,%1,%2,%3}, {%4,%5,%6,%7}, {%8,%9}, {%0,%1,%2,%3};"
        : "+f"(d[0]), "+f"(d[1]), "+f"(d[2]), "+f"(d[3])
        : "r"(a0), "r"(a1), "r"(a2), "r"(a3), "r"(b0), "r"(b1));
}
__device__ __forceinline__ void cpasync16(uint32_t s, const void* g){
    asm volatile("cp.async.cg.shared.global [%0], [%1], 16;" :: "r"(s), "l"(g));
}
__device__ __forceinline__ void red4(float* p, float4 v){
    asm volatile("red.global.add.v4.f32 [%0], {%1,%2,%3,%4};"
                 :: "l"(p), "f"(v.x), "f"(v.y), "f"(v.z), "f"(v.w) : "memory");
}
__device__ __forceinline__ uint64_t mkpol_last(){
    uint64_t p;
    asm("createpolicy.fractional.L2::evict_last.b64 %0, 1.0;" : "=l"(p));
    return p;
}
__device__ __forceinline__ uint64_t mkpol_first(){
    uint64_t p;
    asm("createpolicy.fractional.L2::evict_first.b64 %0, 1.0;" : "=l"(p));
    return p;
}
__device__ __forceinline__ uint4 ldg_pol4(const void* p, uint64_t pol){
    uint4 v;
    asm volatile("ld.global.nc.L2::cache_hint.v4.u32 {%0,%1,%2,%3}, [%4], %5;"
                 : "=r"(v.x), "=r"(v.y), "=r"(v.z), "=r"(v.w) : "l"(p), "l"(pol));
    return v;
}
__device__ __forceinline__ float4 ldg_polf4(const float* p, uint64_t pol){
    float4 v;
    asm volatile("ld.global.nc.L2::cache_hint.v4.f32 {%0,%1,%2,%3}, [%4], %5;"
                 : "=f"(v.x), "=f"(v.y), "=f"(v.z), "=f"(v.w) : "l"(p), "l"(pol));
    return v;
}
__device__ __forceinline__ __half2 h2tanh_(__half2 x){
    uint32_t r, a = *(uint32_t*)&x;
    asm("tanh.approx.f16x2 %0, %1;" : "=r"(r) : "r"(a));
    return *(__half2*)&r;
}
__device__ __forceinline__ __half2 h2ex2_(__half2 x){
    uint32_t r, a = *(uint32_t*)&x;
    asm("ex2.approx.f16x2 %0, %1;" : "=r"(r) : "r"(a));
    return *(__half2*)&r;
}
__device__ __forceinline__ float sigf(float f){
    float t;
    asm("tanh.approx.f32 %0, %1;" : "=f"(t) : "f"(0.5f * f));
    return fmaf(0.5f, t, 0.5f);
}
__device__ __forceinline__ float gact(float f, float s){
    float sp = fmaxf(s, 0.f) + __logf(1.f + __expf(-fabsf(s)));
    return sigf(f) * sp;
}

// ---- prepack ----
__global__ void pack_wbN_kernel(const float* __restrict__ Wf, const float* __restrict__ Ws){
    int idx = blockIdx.x * blockDim.x + threadIdx.x;
    if (idx >= NLAYERS*2*2*5*NPG*32) return;
    int k  = idx & 31;
    int n  = (idx >> 5) % NPG;
    int kc = (idx / (32*NPG)) % 5;
    int sp = (idx / (32*NPG*5)) & 1;
    int hf = (idx / (32*NPG*5*2)) & 1;
    int l  = idx / (32*NPG*5*2*2);
    int kg = kc*32 + k;
    float w = 0.f;
    if (n < NCOL && kg < C){
        int pl, j; colmap(n, pl, j);
        if (j < C){
            int zi = hf ? (C + kg) : kg;
            const float* W = pl ? Ws : Wf;
            w = W[(l*ZDIM + zi)*C + j];
        }
    }
    __nv_bfloat16 hi = __float2bfloat16(w);
    d_wbN[idx] = sp ? __float2bfloat16(w - __bfloat162float(hi)) : hi;
}
__global__ void pack_bph_kernel(const float* __restrict__ bf, const float* __restrict__ bs){
    int idx = blockIdx.x * blockDim.x + threadIdx.x;
    if (idx >= NLAYERS*2*NPG) return;
    int n = idx % NPG, hf = (idx / NPG) & 1, l = idx / (2*NPG);
    float v = 0.f;
    if (hf == 0 && n < NCOL){
        int pl, j; colmap(n, pl, j);
        if (j < C) v = pl ? bs[l*C + j] : bf[l*C + j];
    }
    d_bph[idx] = v;
}
__global__ void pack_w3_kernel(const float* __restrict__ Wf, const float* __restrict__ Ws){
    int idx = blockIdx.x * blockDim.x + threadIdx.x;
    if (idx >= NLAYERS*NCOL) return;
    int n = idx % NCOL, l = idx / NCOL;
    int pl, j; colmap(n, pl, j);
    float v = 0.f;
    if (j < C){ const float* W = pl ? Ws : Wf; v = W[(l*ZDIM + 258)*C + j]; }
    d_w3[idx] = v;
}
__global__ void init_x_kernel(const int* __restrict__ atoms, const float* __restrict__ pos,
                              const float* __restrict__ emb){
    int idx = blockIdx.x * blockDim.x + threadIdx.x;
    if (idx >= NROWS*(XS/4)) return;
    int n = idx / (XS/4), c4 = idx - n*(XS/4);
    float4 v = make_float4(0.f, 0.f, 0.f, 0.f);
    if (n < N_NODES){
        if (c4 < 32) v = *(const float4*)(emb + (size_t)atoms[n]*128 + c4*4);
        else if (c4 == 32) v.x = pos[n*3 + 2];
    }
    *(float4*)(d_xa + (size_t)n*XS + c4*4) = v;
}

// ---- CSR build + degree-ordered schedule ----
__global__ void zero_cnt_kernel(){
    int i = blockIdx.x * blockDim.x + threadIdx.x;
    if (i < N_NODES) d_cnt[i] = 0;
    if (i < 256) d_dh[i] = 0;
}
__global__ void hist_kernel(const int* __restrict__ ei){
    int e = blockIdx.x * blockDim.x + threadIdx.x;
    if (e < N_EDGES) atomicAdd(&d_cnt[ei[N_EDGES + e]], 1);
}
__global__ void scan_kernel(){
    __shared__ int wsum[32];
    __shared__ int carry;
    int tid = threadIdx.x, lane = tid & 31, wid = tid >> 5;
    if (tid == 0) carry = 0;
    __syncthreads();
    for (int base = 0; base < N_NODES; base += 1024){
        int i = base + tid;
        int v = (i < N_NODES) ? d_cnt[i] : 0;
        int x = v;
        #pragma unroll
        for (int d = 1; d < 32; d <<= 1){
            int y = __shfl_up_sync(0xffffffffu, x, d);
            if (lane >= d) x += y;
        }
        if (lane == 31) wsum[wid] = x;
        __syncthreads();
        if (wid == 0){
            int s = wsum[lane];
            #pragma unroll
            for (int d = 1; d < 32; d <<= 1){
                int y = __shfl_up_sync(0xffffffffu, s, d);
                if (lane >= d) s += y;
            }
            wsum[lane] = s;
        }
        __syncthreads();
        int excl = x - v + (wid ? wsum[wid-1] : 0) + carry;
        if (i < N_NODES){ d_rowptr[i] = excl; d_pos[i] = excl; }
        __syncthreads();
        if (tid == 0) carry += wsum[31];
        __syncthreads();
    }
    if (threadIdx.x == 0) d_rowptr[N_NODES] = carry;
}
__global__ void scatter_kernel(const int* __restrict__ ei, const float* __restrict__ pos){
    int e = blockIdx.x * blockDim.x + threadIdx.x;
    if (e >= N_EDGES) return;
    int s = ei[e], d = ei[N_EDGES + e];
    float dx = pos[s*3]-pos[d*3], dy = pos[s*3+1]-pos[d*3+1], dz = pos[s*3+2]-pos[d*3+2];
    float eav = sqrtf(dx*dx + dy*dy + dz*dz);
    int p = atomicAdd(&d_pos[d], 1);
    d_edges[p] = make_int2(s, __float_as_int(eav));
    d_edst[p] = d;
}
__global__ void dhist_kernel(){
    int n = blockIdx.x * blockDim.x + threadIdx.x;
    if (n >= N_NODES) return;
    int d = min(d_cnt[n], 255);
    atomicAdd(&d_dh[d], 1);
}
__global__ void dscan_kernel(){
    if (threadIdx.x == 0){
        int acc = 0;
        for (int d = 255; d >= 0; d--){ d_dpos[d] = acc; acc += d_dh[d]; }
    }
}
__global__ void dorder_kernel(){
    int n = blockIdx.x * blockDim.x + threadIdx.x;
    if (n >= N_NODES) return;
    int d = min(d_cnt[n], 255);
    int p = atomicAdd(&d_dpos[d], 1);
    d_order[p] = n;
}

// ---- node GEMM: A bf16-rounded (hi only), B split hi/lo; 4 MMAs/tile ----
__global__ __launch_bounds__(512, 1)
void node_gemm_kernel(const float* __restrict__ xc, int layer){
    extern __shared__ __align__(16) char smem[];
    uint32_t sb = smem_u32(smem);
    int tid = threadIdx.x, lane = tid & 31, wid = tid >> 5;
    int r0 = lane >> 2, tin = lane & 3;
    int warpM = wid & 3, warpN = wid >> 2;
    int m0 = blockIdx.x * 128;

    {
        int row = tid >> 2, q = tid & 3;
        const float4* xr = (const float4*)(xc + (size_t)(m0 + row)*XS) + q*10;
        char* arow = smem + GSA + row*336 + q*80;
        #pragma unroll
        for (int j = 0; j < 10; j++){
            float4 v = xr[j];
            __nv_bfloat162 h0(__float2bfloat16(v.x), __float2bfloat16(v.y));
            __nv_bfloat162 h1(__float2bfloat16(v.z), __float2bfloat16(v.w));
            *(uint2*)(arow + j*8) = make_uint2(*(uint32_t*)&h0, *(uint32_t*)&h1);
        }
    }

    uint32_t aoff = (uint32_t)((warpM*32 + r0)*336 + tin*4);
    uint32_t boff = (uint32_t)((warpN*72 + r0)*80 + tin*4);
    float* biS = (float*)(smem + GSBI);

    for (int hf = 0; hf < 2; hf++){
        const __nv_bfloat16* wbase = d_wbN + (size_t)((layer*2 + hf)*2) * 5*NPG*32;
        __syncthreads();
        #pragma unroll
        for (int pc = 0; pc < 2; pc++){
            for (int i = tid; i < 2304; i += 512){
                int sp = i / 1152, rr = i % 1152, n = rr >> 2, kv = rr & 3;
                const void* g = wbase + ((size_t)sp*5 + pc)*NPG*32 + n*32 + kv*8;
                cpasync16(sb + GSB + pc*GSBUF + sp*GSSP + n*80 + kv*16, g);
            }
            asm volatile("cp.async.commit_group;" ::: "memory");
        }
        for (int i = tid; i < NPG; i += 512) biS[i] = d_bph[(layer*2 + hf)*NPG + i];

        float acc[2][9][4];
        #pragma unroll
        for (int a = 0; a < 2; a++)
            #pragma unroll
            for (int b = 0; b < 9; b++)
                #pragma unroll
                for (int c = 0; c < 4; c++) acc[a][b][c] = 0.f;

        for (int sc = 0; sc < 5; sc++){
            int buf = sc & 1;
            if (sc == 4) asm volatile("cp.async.wait_group 0;" ::: "memory");
            else         asm volatile("cp.async.wait_group 1;" ::: "memory");
            __syncthreads();
            const char* bbuf = smem + GSB + buf*GSBUF;
            #pragma unroll
            for (int ks = 0; ks < 2; ks++){
                uint32_t ka = (uint32_t)(sc*32 + ks*16)*2;
                const char* ap = smem + GSA + aoff + ka;
                uint32_t ah[2][4];
                #pragma unroll
                for (int mt = 0; mt < 2; mt++){
                    const char* p = ap + mt*5376;
                    ah[mt][0] = *(const uint32_t*)(p);
                    ah[mt][1] = *(const uint32_t*)(p + 2688);
                    ah[mt][2] = *(const uint32_t*)(p + 16);
                    ah[mt][3] = *(const uint32_t*)(p + 2704);
                }
                uint32_t kb = (uint32_t)ks*32;
                #pragma unroll
                for (int nt = 0; nt < 9; nt++){
                    const char* bp = bbuf + boff + nt*640 + kb;
                    uint32_t bh0 = *(const uint32_t*)(bp);
                    uint32_t bh1 = *(const uint32_t*)(bp + 16);
                    uint32_t bl0 = *(const uint32_t*)(bp + GSSP);
                    uint32_t bl1 = *(const uint32_t*)(bp + GSSP + 16);
                    mma16816(acc[0][nt], ah[0][0], ah[0][1], ah[0][2], ah[0][3], bh0, bh1);
                    mma16816(acc[1][nt], ah[1][0], ah[1][1], ah[1][2], ah[1][3], bh0, bh1);
                    mma16816(acc[0][nt], ah[0][0], ah[0][1], ah[0][2], ah[0][3], bl0, bl1);
                    mma16816(acc[1][nt], ah[1][0], ah[1][1], ah[1][2], ah[1][3], bl0, bl1);
                }
            }
            __syncthreads();
            if (sc < 3){
                int nc = sc + 2;
                for (int i = tid; i < 2304; i += 512){
                    int sp = i / 1152, rr = i % 1152, n = rr >> 2, kv = rr & 3;
                    const void* g = wbase + ((size_t)sp*5 + nc)*NPG*32 + n*32 + kv*8;
                    cpasync16(sb + GSB + buf*GSBUF + sp*GSSP + n*80 + kv*16, g);
                }
                asm volatile("cp.async.commit_group;" ::: "memory");
            }
        }

        #pragma unroll
        for (int mt = 0; mt < 2; mt++){
            #pragma unroll
            for (int nt = 0; nt < 9; nt++){
                int col = warpN*72 + nt*8 + tin*2;
                if (col >= NCOL) continue;
                float b0 = biS[col], b1 = biS[col + 1];
                #pragma unroll
                for (int h = 0; h < 2; h++){
                    int row = m0 + warpM*32 + mt*16 + r0 + h*8;
                    float v0 = acc[mt][nt][2*h] + b0;
                    float v1 = acc[mt][nt][2*h+1] + b1;
                    if (hf == 0){
                        *(float2*)(d_P1 + (size_t)row*NCOL + col) = make_float2(v0, v1);
                    } else {
                        if (col < 256)
                            *(__half2*)(d_P2h + (size_t)row*P2S + col) = __floats2half2_rn(v0, v1);
                        else if (col == 256)
                            d_P2t[row*2]     = __float2half(v0);
                        else if (col == 258)
                            d_P2t[row*2 + 1] = __float2half(v0);
                    }
                }
            }
        }
    }
}

// ---- edge phase: warp-per-node, policy-pinned gather, half2-poly softplus ----
__global__ __launch_bounds__(256)
void edge_csr_kernel(const float* __restrict__ xc, float* __restrict__ xn, int layer){
    int lane = threadIdx.x & 31, warp = threadIdx.x >> 5;
    int n = d_order[blockIdx.x * 8 + warp];
    int cb = lane * 8;
    uint64_t pol_l = mkpol_last();
    uint64_t pol_f = mkpol_first();
    const float* w3 = d_w3 + layer * NCOL;
    const float* p1 = d_P1 + (size_t)n * NCOL;
    float4 pa = ldg_polf4(p1 + cb, pol_f);
    float4 pb = ldg_polf4(p1 + cb + 4, pol_f);
    float4 wa = *(const float4*)(w3 + cb);
    float4 wb = *(const float4*)(w3 + cb + 4);
    __half2 f1hA = __floats2half2_rn(0.5f*pa.x, 0.5f*pa.y);
    __half2 f1hB = __floats2half2_rn(0.5f*pb.x, 0.5f*pb.y);
    __half2 wfhA = __floats2half2_rn(0.5f*wa.x, 0.5f*wa.y);
    __half2 wfhB = __floats2half2_rn(0.5f*wb.x, 0.5f*wb.y);
    float s10=pa.z, s11=pa.w, s12=pb.z, s13=pb.w;
    float ws0=wa.z, ws1=wa.w, ws2=wb.z, ws3=wb.w;
    const __half2 h05 = __float2half2_rn(0.5f);
    const __half2 h1  = __float2half2_rn(1.0f);
    const __half2 c0 = __float2half2_rn( 1.442695f);
    const __half2 c1 = __float2half2_rn(-0.713852f);
    const __half2 c2 = __float2half2_rn( 0.426624f);
    const __half2 c3 = __float2half2_rn(-0.204863f);
    const __half2 c4 = __float2half2_rn( 0.049396f);
    int beg = d_rowptr[n], end = d_rowptr[n + 1];
    float a0=0.f, a1=0.f, a2=0.f, a3=0.f;

    #pragma unroll 2
    for (int i = beg; i < end; i++){
        int2 e = d_edges[i];
        float ev = __int_as_float(e.y);
        const __half* q = d_P2h + (size_t)e.x * P2S;
        uint4 w = ldg_pol4(q + cb, pol_l);
        __half2 evh = __float2half2_rn(ev);
        __half2 tA = h2tanh_(__hfma2(*(__half2*)&w.x, h05, __hfma2(evh, wfhA, f1hA)));
        __half2 tB = h2tanh_(__hfma2(*(__half2*)&w.z, h05, __hfma2(evh, wfhB, f1hB)));
        float2 sy = __half22float2(*(__half2*)&w.y);
        float2 sw = __half22float2(*(__half2*)&w.w);
        float s0 = fmaf(ev, ws0, s10) + sy.x;
        float s1 = fmaf(ev, ws1, s11) + sy.y;
        float s2 = fmaf(ev, ws2, s12) + sw.x;
        float s3 = fmaf(ev, ws3, s13) + sw.y;
        __half2 uiA = __floats2half2_rn(fabsf(s0)*-1.44269504f, fabsf(s1)*-1.44269504f);
        __half2 uiB = __floats2half2_rn(fabsf(s2)*-1.44269504f, fabsf(s3)*-1.44269504f);
        __half2 uA = h2ex2_(uiA);
        __half2 uB = h2ex2_(uiB);
        __half2 pA = __hfma2(uA, c4, c3);
        pA = __hfma2(uA, pA, c2); pA = __hfma2(uA, pA, c1); pA = __hfma2(uA, pA, c0);
        pA = __hmul2(uA, pA);
        __half2 pB = __hfma2(uB, c4, c3);
        pB = __hfma2(uB, pB, c2); pB = __hfma2(uB, pB, c1); pB = __hfma2(uB, pB, c0);
        pB = __hmul2(uB, pB);
        float2 lg01 = __half22float2(pA);
        float2 lg23 = __half22float2(pB);
        float sp0 = fmaf(LN2, lg01.x, fmaxf(s0, 0.f));
        float sp1 = fmaf(LN2, lg01.y, fmaxf(s1, 0.f));
        float sp2 = fmaf(LN2, lg23.x, fmaxf(s2, 0.f));
        float sp3 = fmaf(LN2, lg23.y, fmaxf(s3, 0.f));
        float2 tp01 = __half22float2(__hadd2(tA, h1));
        float2 tp23 = __half22float2(__hadd2(tB, h1));
        a0 = fmaf(tp01.x, sp0, a0);
        a1 = fmaf(tp01.y, sp1, a1);
        a2 = fmaf(tp23.x, sp2, a2);
        a3 = fmaf(tp23.y, sp3, a3);
    }

    float* xr = xn + (size_t)n * XS;
    const float* xcr = xc + (size_t)n * XS;
    float4 xv = ldg_polf4(xcr + lane*4, pol_f);
    xv.x = fmaf(0.5f, a0, xv.x);
    xv.y = fmaf(0.5f, a1, xv.y);
    xv.z = fmaf(0.5f, a2, xv.z);
    xv.w = fmaf(0.5f, a3, xv.w);
    *(float4*)(xr + lane*4) = xv;
    if (lane == 0) xr[128] = xcr[128];
}

// ---- tail channel (128): one thread per edge, atomic accumulate ----
__global__ __launch_bounds__(256)
void edge_tail_kernel(float* __restrict__ xn, int layer){
    int e = blockIdx.x * 256 + threadIdx.x;
    int2 ed = d_edges[e];
    int dst = d_edst[e];
    float ev = __int_as_float(ed.y);
    __half2 t2 = *(const __half2*)(d_P2t + ed.x*2);
    float4 pt = *(const float4*)(d_P1 + (size_t)dst*NCOL + 256);
    float wf = d_w3[layer*NCOL + 256];
    float ws = d_w3[layer*NCOL + 258];
    float2 tv = __half22float2(t2);
    float m = gact(pt.x + tv.x + ev*wf, pt.z + tv.y + ev*ws);
    atomicAdd(xn + (size_t)dst*XS + 128, m);
}

// ---- pooling + head ----
__global__ void zero_pool_kernel(){
    int idx = blockIdx.x * blockDim.x + threadIdx.x;
    if (idx < NUM_GRAPHS*PLN) d_gsum[idx] = 0.f;
    if (idx < NUM_GRAPHS)     d_gcnt[idx] = 0.f;
}
__global__ __launch_bounds__(256)
void pool_kernel(const float* __restrict__ x, const int* __restrict__ batch){
    int lane = threadIdx.x & 31, warp = threadIdx.x >> 5;
    int n = blockIdx.x * 8 + warp;
    int b = batch[n];
    const float* xr = x + (size_t)n * XS;
    float4 v = *(const float4*)(xr + lane*4);
    red4(&d_gsum[b*PLN + lane*4], v);
    if (lane == 0) atomicAdd(&d_gsum[b*PLN + 128], xr[128]);
    if (lane == 1) atomicAdd(&d_gcnt[b], 1.f);
}
__global__ void head_kernel(const float* __restrict__ Wfc, const float* __restrict__ bfc,
                            const float* __restrict__ Wout, const float* __restrict__ bout,
                            float* __restrict__ out){
    int g = blockIdx.x, t = threadIdx.x;
    __shared__ float row[C];
    __shared__ float red[256];
    if (t < C) row[t] = d_gsum[g*PLN + t] / fmaxf(d_gcnt[g], 1.f);
    __syncthreads();
    for (int l = 0; l < 3; l++){
        float y = 0.f;
        if (t < C){
            #pragma unroll 4
            for (int k = 0; k < C; k++) y = fmaf(row[k], Wfc[(l*C + k)*C + t], y);
            y += bfc[l*C + t];
        }
        __syncthreads();
        if (t < C) row[t] = y;
        __syncthreads();
    }
    red[t] = (t < C) ? row[t]*Wout[t] : 0.f;
    __syncthreads();
    for (int s = 128; s > 0; s >>= 1){ if (t < s) red[t] += red[t + s]; __syncthreads(); }
    if (t == 0) out[g] = red[0] + bout[0];
}

extern "C" void kernel_launch(void* const* d_in, const int* in_sizes, int n_in,
                              void* d_out, int out_size){
    const int*   atoms = (const int*)d_in[0];
    const float* pos   = (const float*)d_in[1];
    const int*   ei    = (const int*)d_in[2];
    const int*   batch = (const int*)d_in[3];
    const float* emb   = (const float*)d_in[4];
    const float* Wf    = (const float*)d_in[5];
    const float* bf    = (const float*)d_in[6];
    const float* Ws    = (const float*)d_in[7];
    const float* bs    = (const float*)d_in[8];
    const float* Wfc   = (const float*)d_in[9];
    const float* bfc   = (const float*)d_in[10];
    const float* Wout  = (const float*)d_in[11];
    const float* bout  = (const float*)d_in[12];
    float* out = (float*)d_out;

    cudaFuncSetAttribute(node_gemm_kernel,
                         cudaFuncAttributeMaxDynamicSharedMemorySize, GSMEM);

    float *xa, *xb;
    cudaGetSymbolAddress((void**)&xa, d_xa);
    cudaGetSymbolAddress((void**)&xb, d_xb);

    pack_wbN_kernel<<<(NLAYERS*2*2*5*NPG*32 + 255)/256, 256>>>(Wf, Ws);
    pack_bph_kernel<<<(NLAYERS*2*NPG + 255)/256, 256>>>(bf, bs);
    pack_w3_kernel<<<(NLAYERS*NCOL + 255)/256, 256>>>(Wf, Ws);
    init_x_kernel<<<(NROWS*(XS/4) + 255)/256, 256>>>(atoms, pos, emb);

    zero_cnt_kernel<<<(N_NODES + 255)/256, 256>>>();
    hist_kernel<<<(N_EDGES + 255)/256, 256>>>(ei);
    scan_kernel<<<1, 1024>>>();
    scatter_kernel<<<(N_EDGES + 255)/256, 256>>>(ei, pos);
    dhist_kernel<<<(N_NODES + 255)/256, 256>>>();
    dscan_kernel<<<1, 32>>>();
    dorder_kernel<<<(N_NODES + 255)/256, 256>>>();

    float* cur = xa;
    float* nxt = xb;
    for (int l = 0; l < NLAYERS; l++){
        node_gemm_kernel<<<NROWS/128, 512, GSMEM>>>(cur, l);
        edge_csr_kernel<<<N_NODES/8, 256>>>(cur, nxt, l);
        edge_tail_kernel<<<N_EDGES/256, 256>>>(nxt, l);
        float* tmp = cur; cur = nxt; nxt = tmp;
    }

    zero_pool_kernel<<<(NUM_GRAPHS*PLN + 255)/256, 256>>>();
    pool_kernel<<<N_NODES/8, 256>>>(cur, batch);
    head_kernel<<<NUM_GRAPHS, 256>>>(Wfc, bfc, Wout, bout, out);
}